// round 14
// baseline (speedup 1.0000x reference)
#include <cuda_runtime.h>
#include <cuda_fp16.h>
#include <cstdint>

#define BATCH 4
#define EDIM 1024
#define CDIM 768
#define TLEN 1024
#define SLEN 1024
#define NH 16
#define DH 64
#define EPSV 1e-5f

// ---------------- scratch (static device globals; no allocation) ----------------
__device__ __half g_wnq[EDIM * EDIM];
__device__ __half g_wnkv[2 * EDIM * CDIM];              // [wnk ; wnv]
__device__ __half g_wno[EDIM * EDIM];
__device__ __half g_xr[BATCH * TLEN * EDIM];            // x^T  [B][T][E] fp16
__device__ __half g_cr[BATCH * SLEN * CDIM];            // ctx^T [B][S][C] fp16
__device__ __half g_q[BATCH * TLEN * EDIM];             // q [B][T][E]
__device__ __half g_k[BATCH * SLEN * EDIM];             // k [B][S][E]
__device__ __half g_v[BATCH * EDIM * SLEN];             // v [B][E][S]
__device__ __half g_p[(long)BATCH * NH * TLEN * SLEN];  // P [b,h][t][s] fp16
__device__ float g_rp[BATCH * NH * SLEN * 8];           // per-t-tile column partials
__device__ float g_r[BATCH * NH * SLEN];                // 1/rowsum (or 0)
__device__ __half g_att[BATCH * TLEN * EDIM];           // att [B][T][E]
__device__ unsigned char g_mask[BATCH * TLEN];
__device__ unsigned char g_mctx[BATCH * SLEN];

__device__ __forceinline__ uint32_t smem_u32(const void* p) {
    uint32_t a;
    asm("{ .reg .u64 t; cvta.to.shared.u64 t, %1; cvt.u32.u64 %0, t; }" : "=r"(a) : "l"(p));
    return a;
}
__device__ __forceinline__ uint32_t packh2(float lo, float hi) {
    __half2 h = __floats2half2_rn(lo, hi);
    return *(uint32_t*)&h;
}
#define CP16(dst, src) asm volatile("cp.async.cg.shared.global [%0], [%1], 16;" :: "r"(dst), "l"(src))
#define CPCOMMIT()     asm volatile("cp.async.commit_group;" ::: "memory")
#define CPWAIT(N)      asm volatile("cp.async.wait_group %0;" :: "n"(N) : "memory")

#define MMA_F16(d, a, b) \
    asm volatile("mma.sync.aligned.m16n8k16.row.col.f32.f16.f16.f32 " \
                 "{%0,%1,%2,%3}, {%4,%5,%6,%7}, {%8,%9}, {%0,%1,%2,%3};" \
                 : "+f"((d)[0]), "+f"((d)[1]), "+f"((d)[2]), "+f"((d)[3]) \
                 : "r"((a)[0]), "r"((a)[1]), "r"((a)[2]), "r"((a)[3]), \
                   "r"((b)[0]), "r"((b)[1]))

#define LDSM4(r0, r1, r2, r3, addr) \
    asm volatile("ldmatrix.sync.aligned.m8n8.x4.shared.b16 {%0,%1,%2,%3}, [%4];" \
                 : "=r"(r0), "=r"(r1), "=r"(r2), "=r"(r3) : "r"(addr))

// ---------------- GEMM parameter set ----------------
struct GP {
    const void* A; int aDiv; long aStrZa, aStrZb; int lda;
    const void* B; int bDiv; long bStrZa, bStrZb; int ldb;
    void* C; int cDiv; long cStrZa, cStrZb; int ldc;
    int K;
    const float* bias; int biasOnM;
    const unsigned char* mask; int maskOnM; int maskDiv; int maskLd;
    const float* res; long resStride;
    float* rp;                       // EPI==3 only: column-partial buffer
};

// ================= fp16 mma GEMM body: BK=64, single-sync pipeline =================
// C[m,n] = sum_k A[m,k] * B[n,k]   (fp16 operands, fp32 accum)
// smem: A [m][k] stride 72, B [n][k] stride 72; fragments via ldmatrix.x4.
// 4 warps; warp tile WM x 64 (WM in {64, 32}); (BM/WM)*(BN/64) must equal 4.
// EPI 0: conv (bias on m or n; mask->0 on m or n; + residual when CBYTES==4)
// EPI 2: plain fp16 store
// EPI 3: exp-scores (c = mask[m] ? h(expf(c)) : 0) + per-COLUMN partial sums -> rp
template <int EPI, int BM, int BN, int WM, int NS, int CBYTES>
__device__ __forceinline__ void gemm_body(const GP& P, int ytile) {
    constexpr int BK = 64;
    constexpr int STR = BK + 8;             // 72 halves per row
    constexpr int AFL = BM * STR;
    constexpr int BFL = BN * STR;
    constexpr int STG = AFL + BFL;          // halves per stage
    constexpr int NWM = BM / WM;
    constexpr int MF = WM / 16;
    constexpr int NF = 8;

    extern __shared__ char smch[];
    uint32_t sbase = smem_u32(smch);
    int tid = threadIdx.x, wid = tid >> 5, lane = tid & 31;
    int z = blockIdx.z;
    const __half* A = (const __half*)P.A + (z / P.aDiv) * P.aStrZa + (z % P.aDiv) * P.aStrZb;
    const __half* B = (const __half*)P.B + (z / P.bDiv) * P.bStrZa + (z % P.bDiv) * P.bStrZb;
    long mBase = (long)ytile * BM, nBase = (long)blockIdx.x * BN;
    int lda = P.lda, ldb = P.ldb, ldc = P.ldc;

    float acc[MF][NF][4];
#pragma unroll
    for (int i = 0; i < MF; ++i)
#pragma unroll
        for (int j = 0; j < NF; ++j)
#pragma unroll
            for (int t = 0; t < 4; ++t) acc[i][j][t] = 0.f;

    int nIter = P.K / BK;

    auto issue = [&](int stage, int k0) {
        uint32_t aoff = sbase + stage * STG * 2;
#pragma unroll
        for (int r = 0; r < BM / 16; ++r) {       // BM rows x 8 chunks / 128 thr
            int lin = tid + 128 * r;
            int m = lin >> 3, kc = (lin & 7) * 8;
            CP16(aoff + (m * STR + kc) * 2, &A[(mBase + m) * (long)lda + k0 + kc]);
        }
        uint32_t boff = sbase + (stage * STG + AFL) * 2;
#pragma unroll
        for (int r = 0; r < BN / 16; ++r) {
            int lin = tid + 128 * r;
            int n = lin >> 3, kc = (lin & 7) * 8;
            CP16(boff + (n * STR + kc) * 2, &B[(nBase + n) * (long)ldb + k0 + kc]);
        }
    };

    int warpM = wid % NWM, warpN = wid / NWM;
    int mW = warpM * WM, nW = warpN * 64;
    int c4 = lane & 3, r4 = lane >> 2;
    int quad = lane >> 3, lrow = lane & 7;

    // ldmatrix role-based per-thread half-offsets (within a stage)
    uint32_t aRole[MF], bRole[NF / 2];
#pragma unroll
    for (int mf = 0; mf < MF; ++mf)
        aRole[mf] = (uint32_t)((mW + 16 * mf + (quad & 1) * 8 + lrow) * STR + (quad >> 1) * 8);
#pragma unroll
    for (int p = 0; p < NF / 2; ++p)
        bRole[p] = (uint32_t)((nW + 16 * p + (quad >> 1) * 8 + lrow) * STR + (quad & 1) * 8);

    auto compute = [&](int stage) {
        uint32_t As_b = sbase + stage * STG * 2;
        uint32_t Bs_b = As_b + AFL * 2;
#pragma unroll
        for (int kk = 0; kk < BK; kk += 16) {
            uint32_t a[MF][4];
#pragma unroll
            for (int mf = 0; mf < MF; ++mf)
                LDSM4(a[mf][0], a[mf][1], a[mf][2], a[mf][3], As_b + (aRole[mf] + kk) * 2);
            uint32_t b[NF][2];
#pragma unroll
            for (int p = 0; p < NF / 2; ++p)
                LDSM4(b[2 * p][0], b[2 * p][1], b[2 * p + 1][0], b[2 * p + 1][1],
                      Bs_b + (bRole[p] + kk) * 2);
#pragma unroll
            for (int mf = 0; mf < MF; ++mf)
#pragma unroll
                for (int nf = 0; nf < NF; ++nf)
                    MMA_F16(acc[mf][nf], a[mf], b[nf]);
        }
    };

    if (NS == 1) {
        for (int it = 0; it < nIter; ++it) {
            issue(0, it * BK);
            CPCOMMIT();
            CPWAIT(0);
            __syncthreads();
            compute(0);
            if (it + 1 < nIter) __syncthreads();
        }
    } else {
        for (int s = 0; s < NS - 1; ++s) {
            if (s < nIter) issue(s, s * BK);
            CPCOMMIT();
        }
        // single-sync mainloop: top sync of iter it+1 proves all threads finished
        // compute(it) before anyone overwrites stage it%NS.
        for (int it = 0; it < nIter; ++it) {
            CPWAIT(NS - 2);
            __syncthreads();
            compute(it % NS);
            int nx = it + NS - 1;
            if (nx < nIter) issue(nx % NS, nx * BK);
            CPCOMMIT();
        }
    }

    // ---- epilogue ----
    int mb = z / P.maskDiv;
    float bn[NF][2];
    unsigned char mn[NF][2];
    if (EPI == 0) {
#pragma unroll
        for (int nf = 0; nf < NF; ++nf) {
            long n = nBase + nW + nf * 8 + 2 * c4;
            bn[nf][0] = P.biasOnM ? 0.f : P.bias[n];
            bn[nf][1] = P.biasOnM ? 0.f : P.bias[n + 1];
            mn[nf][0] = P.maskOnM ? 1 : P.mask[(long)mb * P.maskLd + n];
            mn[nf][1] = P.maskOnM ? 1 : P.mask[(long)mb * P.maskLd + n + 1];
        }
    }
    float rsumN[NF * 2];
#pragma unroll
    for (int q = 0; q < NF * 2; ++q) rsumN[q] = 0.f;

#pragma unroll
    for (int mf = 0; mf < MF; ++mf) {
#pragma unroll
        for (int half = 0; half < 2; ++half) {
            long m = mBase + mW + mf * 16 + r4 + half * 8;
            float bvm = (EPI == 0 && P.biasOnM) ? P.bias[m] : 0.f;
            bool mOK = true;
            if ((EPI == 0 || EPI == 3) && P.maskOnM)
                mOK = P.mask[(long)mb * P.maskLd + m] != 0;
#pragma unroll
            for (int nf = 0; nf < NF; ++nf) {
                long n = nBase + nW + nf * 8 + 2 * c4;
                float v0 = acc[mf][nf][half * 2 + 0];
                float v1 = acc[mf][nf][half * 2 + 1];
                if (EPI == 0) {
                    if (P.biasOnM) { v0 += bvm; v1 += bvm; }
                    else { v0 += bn[nf][0]; v1 += bn[nf][1]; }
                    if (P.maskOnM) { if (!mOK) { v0 = 0.f; v1 = 0.f; } }
                    else { if (!mn[nf][0]) v0 = 0.f; if (!mn[nf][1]) v1 = 0.f; }
                } else if (EPI == 3) {
                    __half h0 = __float2half_rn(__expf(v0));
                    __half h1 = __float2half_rn(__expf(v1));
                    v0 = mOK ? __half2float(h0) : 0.f;
                    v1 = mOK ? __half2float(h1) : 0.f;
                    rsumN[nf * 2 + 0] += v0;
                    rsumN[nf * 2 + 1] += v1;
                }
                if (CBYTES == 4) {
                    float* Cf = (float*)P.C + (z / P.cDiv) * P.cStrZa + (z % P.cDiv) * P.cStrZb;
                    if (EPI == 0 && P.res) {
                        v0 += P.res[z * P.resStride + m * ldc + n];
                        v1 += P.res[z * P.resStride + m * ldc + n + 1];
                    }
                    float2 o; o.x = v0; o.y = v1;
                    *(float2*)&Cf[m * ldc + n] = o;
                } else {
                    __half* Ch = (__half*)P.C + (z / P.cDiv) * P.cStrZa + (z % P.cDiv) * P.cStrZb;
                    *(uint32_t*)&Ch[m * ldc + n] = packh2(v0, v1);
                }
            }
        }
    }
    if (EPI == 3) {
        // column sums: reduce over r4 lanes (rows), then across warpM warps via smem
#pragma unroll
        for (int q = 0; q < NF * 2; ++q) {
            float v = rsumN[q];
            v += __shfl_xor_sync(0xFFFFFFFFu, v, 4);
            v += __shfl_xor_sync(0xFFFFFFFFu, v, 8);
            v += __shfl_xor_sync(0xFFFFFFFFu, v, 16);
            rsumN[q] = v;
        }
        __syncthreads();
        float* red = (float*)smch;           // [NWM][BN]
        if (r4 == 0) {
#pragma unroll
            for (int nf = 0; nf < NF; ++nf) {
                int nl = nW + nf * 8 + 2 * c4;
                red[warpM * BN + nl] = rsumN[nf * 2 + 0];
                red[warpM * BN + nl + 1] = rsumN[nf * 2 + 1];
            }
        }
        __syncthreads();
        if (tid < BN) {
            float s = red[tid];
#pragma unroll
            for (int w = 1; w < NWM; ++w) s += red[w * BN + tid];
            P.rp[((long)z * SLEN + nBase + tid) * 8 + ytile] = s;
        }
    }
}

// kernel wrapper with uniform triple-param-set dispatch on blockIdx.y
template <int EPI, int BM, int BN, int WM, int NS, int CBYTES>
__global__ __launch_bounds__(128) void mma_gemm(GP p0, GP p1, GP p2, int y1, int y2) {
    int y = blockIdx.y;
    if (y < y1) gemm_body<EPI, BM, BN, WM, NS, CBYTES>(p0, y);
    else if (y < y2) gemm_body<EPI, BM, BN, WM, NS, CBYTES>(p1, y - y1);
    else gemm_body<EPI, BM, BN, WM, NS, CBYTES>(p2, y - y2);
}

// ================= preamble megakernel: canon + transpose x + transpose ctx + ws ======
__device__ void canon_body(const unsigned char* __restrict__ raw,
                           unsigned char* __restrict__ out, int n, int* flag) {
    if (threadIdx.x == 0) *flag = 0;
    __syncthreads();
    int local = 0;
    for (int i = threadIdx.x; i < n; i += 256)
        if ((i & 3) != 0 && raw[i] != 0) local = 1;
    if (local) atomicOr(flag, 1);
    __syncthreads();
    bool is_bool = (*flag != 0);
    for (int i = threadIdx.x; i < n; i += 256)
        out[i] = is_bool ? raw[i] : raw[4 * i];
}

__device__ void transpose_body(const float* __restrict__ in, __half* __restrict__ out,
                               int R, int C, int idx, float* tile /* 32x33 */) {
    int nxb = C / 32;
    int per = nxb * (R / 32);
    int b = idx / per;
    int rem = idx % per;
    int by = rem / nxb, bx = rem % nxb;
    const float* src = in + (long)b * R * C;
    __half* dst = out + (long)b * R * C;
    int c0 = bx * 32, r0 = by * 32;
    int tx = threadIdx.x & 31, ty = threadIdx.x >> 5;   // 32 x 8
#pragma unroll
    for (int i = 0; i < 32; i += 8)
        tile[(ty + i) * 33 + tx] = src[(long)(r0 + ty + i) * C + c0 + tx];
    __syncthreads();
#pragma unroll
    for (int i = 0; i < 32; i += 8)
        dst[(long)(c0 + ty + i) * R + r0 + tx] = __float2half_rn(tile[tx * 33 + ty + i]);
}

__device__ void ws_body(const float* __restrict__ w, __half* __restrict__ outp,
                        int I, int o, float* sh /* >=16 floats */) {
    const float* row = w + (long)o * I;
    float s = 0.f, ss = 0.f;
    for (int i = threadIdx.x; i < I; i += 256) {
        float v = row[i];
        s += v; ss += v * v;
    }
#pragma unroll
    for (int off = 16; off; off >>= 1) {
        s += __shfl_xor_sync(0xFFFFFFFFu, s, off);
        ss += __shfl_xor_sync(0xFFFFFFFFu, ss, off);
    }
    int wid = threadIdx.x >> 5;
    if ((threadIdx.x & 31) == 0) { sh[wid] = s; sh[8 + wid] = ss; }
    __syncthreads();
    if (threadIdx.x == 0) {
        float ts = 0.f, tss = 0.f;
        for (int i = 0; i < 8; i++) { ts += sh[i]; tss += sh[8 + i]; }
        float mu = ts / (float)I;
        float var = tss / (float)I - mu * mu;
        sh[0] = mu; sh[1] = rsqrtf(var + EPSV);
    }
    __syncthreads();
    float mu = sh[0], inv = sh[1];
    for (int i = threadIdx.x; i < I; i += 256)
        outp[(long)o * I + i] = __float2half_rn((row[i] - mu) * inv);
}

#define NB_TX (32 * 32 * BATCH)     // 4096
#define NB_TC (32 * 24 * BATCH)     // 3072
__global__ __launch_bounds__(256) void preamble_kernel(
    const float* __restrict__ x, const float* __restrict__ ctx,
    const unsigned char* __restrict__ mask_raw, const unsigned char* __restrict__ mctx_raw,
    const float* __restrict__ qw, const float* __restrict__ kw,
    const float* __restrict__ vw, const float* __restrict__ ow,
    __half* __restrict__ xr, __half* __restrict__ cr,
    unsigned char* __restrict__ mask, unsigned char* __restrict__ mctx,
    __half* __restrict__ wnq, __half* __restrict__ wnkv, __half* __restrict__ wno)
{
    __shared__ float shm[32 * 33];
    int b = blockIdx.x;
    if (b < 2) {
        canon_body(b ? mctx_raw : mask_raw, b ? mctx : mask, BATCH * TLEN, (int*)shm);
    } else if (b < 2 + NB_TX) {
        transpose_body(x, xr, EDIM, TLEN, b - 2, shm);
    } else if (b < 2 + NB_TX + NB_TC) {
        transpose_body(ctx, cr, CDIM, SLEN, b - 2 - NB_TX, shm);
    } else {
        int idx = b - 2 - NB_TX - NB_TC;
        int c = idx >> 10, o = idx & 1023;
        const float* w; __half* outp; int I;
        if (c == 0) { w = qw; outp = wnq; I = EDIM; }
        else if (c == 1) { w = kw; outp = wnkv; I = CDIM; }
        else if (c == 2) { w = vw; outp = wnkv + EDIM * CDIM; I = CDIM; }
        else { w = ow; outp = wno; I = EDIM; }
        ws_body(w, outp, I, o, shm);
    }
}

// ---------------- per-head LayerNorm over dh=64 ----------------
// c=0: q [B][T][E] contiguous dh (scale 1/256); c=1: k [B][S][E]; c=2: v [B][E][S] strided
__global__ void ln_kernel(__half* __restrict__ qbuf, __half* __restrict__ kbuf,
                          __half* __restrict__ vbuf,
                          const float* __restrict__ gq, const float* __restrict__ bq,
                          const float* __restrict__ gk, const float* __restrict__ bk,
                          const float* __restrict__ gv, const float* __restrict__ bv) {
    int c = blockIdx.y / (BATCH * NH);
    int bh = blockIdx.y % (BATCH * NH);
    int b = bh / NH, h = bh % NH;
    int l = blockIdx.x * blockDim.x + threadIdx.x;
    float vals[DH];
    float s = 0.f, ss = 0.f;
    if (c < 2) {
        __half* base = (c == 0 ? qbuf : kbuf) + ((long)b * TLEN + l) * EDIM + h * DH;
        const float* g = c == 0 ? gq : gk;
        const float* bt = c == 0 ? bq : bk;
        float scale = c == 0 ? (1.f / 256.f) : 1.f;
#pragma unroll
        for (int i = 0; i < 8; ++i) {
            uint4 u = ((const uint4*)base)[i];
            const __half2* hp = (const __half2*)&u;
#pragma unroll
            for (int j = 0; j < 4; ++j) {
                float2 f = __half22float2(hp[j]);
                vals[i * 8 + j * 2] = f.x;
                vals[i * 8 + j * 2 + 1] = f.y;
                s += f.x + f.y;
                ss += f.x * f.x + f.y * f.y;
            }
        }
        float mu = s * (1.f / DH);
        float var = ss * (1.f / DH) - mu * mu;
        float inv = rsqrtf(var + EPSV);
#pragma unroll
        for (int i = 0; i < 8; ++i) {
            uint4 u;
            uint32_t* up = (uint32_t*)&u;
#pragma unroll
            for (int j = 0; j < 4; ++j) {
                int d0 = i * 8 + j * 2;
                up[j] = packh2(((vals[d0] - mu) * inv * g[d0] + bt[d0]) * scale,
                               ((vals[d0 + 1] - mu) * inv * g[d0 + 1] + bt[d0 + 1]) * scale);
            }
            ((uint4*)base)[i] = u;
        }
    } else {
        __half* base = vbuf + (long)b * EDIM * SLEN + (long)h * DH * SLEN + l;
#pragma unroll
        for (int d = 0; d < DH; d++) {
            float v = __half2float(base[(long)d * SLEN]);
            vals[d] = v;
            s += v; ss += v * v;
        }
        float mu = s * (1.f / DH);
        float var = ss * (1.f / DH) - mu * mu;
        float inv = rsqrtf(var + EPSV);
#pragma unroll
        for (int d = 0; d < DH; d++)
            base[(long)d * SLEN] = __float2half_rn((vals[d] - mu) * inv * gv[d] + bv[d]);
    }
}

// ---------------- finalize r: r[i] = mctx && sum>0 ? 1/sum(rp[i][0..7]) : 0 ----------------
__global__ void finalize_r(const float* __restrict__ rp, float* __restrict__ r,
                           const unsigned char* __restrict__ mctx) {
    int i = blockIdx.x * blockDim.x + threadIdx.x;     // 0..65535
    float4 a = ((const float4*)rp)[i * 2];
    float4 b = ((const float4*)rp)[i * 2 + 1];
    float s = ((a.x + a.y) + (a.z + a.w)) + ((b.x + b.y) + (b.z + b.w));
    int bidx = i >> 14, sidx = i & (SLEN - 1);
    r[i] = (mctx[bidx * SLEN + sidx] && s > 0.f) ? (1.f / s) : 0.f;
}

// ---------------- v' = h(v * r[b,h,s]) in-place (fp16) ----------------
__global__ void vscale_kernel(__half* __restrict__ vbuf, const float* __restrict__ r) {
    long i = (long)blockIdx.x * blockDim.x + threadIdx.x;   // 4-half groups over [B][E][S]
    long fi = i * 4;
    int b = (int)(fi / ((long)EDIM * SLEN));
    long rem = fi % ((long)EDIM * SLEN);
    int e = (int)(rem / SLEN), s = (int)(rem % SLEN);
    int h = e / DH;
    __half* vp = vbuf + (long)b * EDIM * SLEN + (long)e * SLEN + s;
    float4 rv = *(const float4*)&r[((long)b * NH + h) * SLEN + s];
    uint2 v = *(uint2*)vp;
    __half2 v01 = *(__half2*)&v.x, v23 = *(__half2*)&v.y;
    uint2 o;
    o.x = packh2(__half2float(v01.x) * rv.x, __half2float(v01.y) * rv.y);
    o.y = packh2(__half2float(v23.x) * rv.z, __half2float(v23.y) * rv.w);
    *(uint2*)vp = o;
}

// ---------------- launch ----------------
extern "C" void kernel_launch(void* const* d_in, const int* in_sizes, int n_in,
                              void* d_out, int out_size) {
    const float* x = (const float*)d_in[0];
    const float* ctx = (const float*)d_in[1];
    const unsigned char* mask_raw = (const unsigned char*)d_in[2];
    const unsigned char* mctx_raw = (const unsigned char*)d_in[3];
    const float* qw = (const float*)d_in[4];
    const float* qb = (const float*)d_in[5];
    const float* kw = (const float*)d_in[6];
    const float* kb = (const float*)d_in[7];
    const float* vw = (const float*)d_in[8];
    const float* vb = (const float*)d_in[9];
    const float* ow = (const float*)d_in[10];
    const float* ob = (const float*)d_in[11];
    const float* gq = (const float*)d_in[12];
    const float* bq = (const float*)d_in[13];
    const float* gk = (const float*)d_in[14];
    const float* bk = (const float*)d_in[15];
    const float* gv = (const float*)d_in[16];
    const float* bv = (const float*)d_in[17];
    float* out = (float*)d_out;

    __half *wnq, *wnkv, *wno, *xr, *cr, *qbuf, *kbuf, *vbuf, *pbuf, *abuf;
    float *rpbuf, *rbuf;
    unsigned char *mask, *mctx;
    cudaGetSymbolAddress((void**)&wnq, g_wnq);
    cudaGetSymbolAddress((void**)&wnkv, g_wnkv);
    cudaGetSymbolAddress((void**)&wno, g_wno);
    cudaGetSymbolAddress((void**)&xr, g_xr);
    cudaGetSymbolAddress((void**)&cr, g_cr);
    cudaGetSymbolAddress((void**)&qbuf, g_q);
    cudaGetSymbolAddress((void**)&kbuf, g_k);
    cudaGetSymbolAddress((void**)&vbuf, g_v);
    cudaGetSymbolAddress((void**)&pbuf, g_p);
    cudaGetSymbolAddress((void**)&rpbuf, g_rp);
    cudaGetSymbolAddress((void**)&rbuf, g_r);
    cudaGetSymbolAddress((void**)&abuf, g_att);
    cudaGetSymbolAddress((void**)&mask, g_mask);
    cudaGetSymbolAddress((void**)&mctx, g_mctx);

    __half* wnk = wnkv;
    __half* wnv = wnkv + EDIM * CDIM;

    const int SM_PROJ = 3 * (128 + 128) * 72 * 2;   // 110592, NS=3
    const int SM_SC = 1 * (128 + 128) * 72 * 2;     // 36864,  NS=1
    const int SM_AV = 2 * (128 + 64) * 72 * 2;      // 55296,  NS=2
    const int SM_OP = 3 * (128 + 128) * 72 * 2;     // 110592, NS=3
    cudaFuncSetAttribute((const void*)mma_gemm<0, 128, 128, 64, 3, 2>,
                         cudaFuncAttributeMaxDynamicSharedMemorySize, SM_PROJ);
    cudaFuncSetAttribute((const void*)mma_gemm<3, 128, 128, 64, 1, 2>,
                         cudaFuncAttributeMaxDynamicSharedMemorySize, SM_SC);
    cudaFuncSetAttribute((const void*)mma_gemm<2, 128, 64, 32, 2, 2>,
                         cudaFuncAttributeMaxDynamicSharedMemorySize, SM_AV);
    cudaFuncSetAttribute((const void*)mma_gemm<0, 128, 128, 64, 3, 4>,
                         cudaFuncAttributeMaxDynamicSharedMemorySize, SM_OP);

    // 0+1. preamble: canon masks + transpose/round x,ctx + weight standardization
    preamble_kernel<<<2 + NB_TX + NB_TC + 4 * EDIM, 256>>>(
        x, ctx, mask_raw, mctx_raw, qw, kw, vw, ow,
        xr, cr, mask, mctx, wnq, wnkv, wno);

    // 2. merged Q + K + V projections: one launch, y-dispatch 8|8|8
    GP pQ = { xr, 1, (long)TLEN * EDIM, 0, EDIM,
              wnq, 1, 0, 0, EDIM,
              qbuf, 1, (long)TLEN * EDIM, 0, EDIM,
              EDIM, qb, 0, mask, 1, 1, TLEN, nullptr, 0, nullptr };
    GP pK = { cr, 1, (long)SLEN * CDIM, 0, CDIM,
              wnk, 1, 0, 0, CDIM,
              kbuf, 1, (long)SLEN * EDIM, 0, EDIM,
              CDIM, kb, 0, mctx, 1, 1, SLEN, nullptr, 0, nullptr };
    GP pV = { wnv, 1, 0, 0, CDIM,
              cr, 1, (long)SLEN * CDIM, 0, CDIM,
              vbuf, 1, (long)EDIM * SLEN, 0, SLEN,
              CDIM, vb, 1, mctx, 0, 1, SLEN, nullptr, 0, nullptr };
    mma_gemm<0, 128, 128, 64, 3, 2><<<dim3(8, 24, BATCH), 128, SM_PROJ>>>(pQ, pK, pV, 8, 16);

    // 3. per-head LayerNorm over dh (q scaled by 1/256)
    ln_kernel<<<dim3(TLEN / 128, 3 * BATCH * NH), 128>>>(qbuf, kbuf, vbuf,
                                                         gq, bq, gk, bk, gv, bv);

    // 4. P[t,s] = mask[t] ? exp(sum_d q'[t,d] k[s,d]) : 0, + column partials -> rp
    GP pS = { qbuf, NH, (long)TLEN * EDIM, DH, EDIM,
              kbuf, NH, (long)SLEN * EDIM, DH, EDIM,
              pbuf, 1, (long)TLEN * SLEN, 0, SLEN,
              DH, nullptr, 0, mask, 1, NH, TLEN, nullptr, 0, rpbuf };
    mma_gemm<3, 128, 128, 64, 1, 2><<<dim3(SLEN / 128, TLEN / 128, BATCH * NH), 128, SM_SC>>>(
        pS, pS, pS, 1 << 30, 1 << 30);

    // 5. finalize r; v' = v * r
    finalize_r<<<BATCH * NH * SLEN / 256, 256>>>(rpbuf, rbuf, mctx);
    vscale_kernel<<<BATCH * EDIM * SLEN / 4 / 256, 256>>>(vbuf, rbuf);

    // 6. att[t,d] = sum_s P[t,s] v'[d,s]  -> att [B][T][E]  (128x64 tiles, 512 CTAs)
    GP pA = { pbuf, 1, (long)TLEN * SLEN, 0, SLEN,
              vbuf, NH, (long)EDIM * SLEN, (long)DH * SLEN, SLEN,
              abuf, NH, (long)TLEN * EDIM, DH, EDIM,
              SLEN, nullptr, 0, mask, 1, 1, TLEN, nullptr, 0, nullptr };
    mma_gemm<2, 128, 64, 32, 2, 2><<<dim3(1, TLEN / 128, BATCH * NH), 128, SM_AV>>>(
        pA, pA, pA, 1 << 30, 1 << 30);

    // 7. out[e,t] = sum_e' wno[e,e'] att[t,e'] + ob + mask + x
    GP pO = { wno, 1, 0, 0, EDIM,
              abuf, 1, (long)TLEN * EDIM, 0, EDIM,
              out, 1, (long)EDIM * TLEN, 0, TLEN,
              EDIM, ob, 1, mask, 0, 1, TLEN, x, (long)EDIM * TLEN, nullptr };
    mma_gemm<0, 128, 128, 64, 3, 4><<<dim3(TLEN / 128, EDIM / 128, BATCH), 128, SM_OP>>>(
        pO, pO, pO, 1 << 30, 1 << 30);
}

// round 15
// speedup vs baseline: 1.0277x; 1.0277x over previous
#include <cuda_runtime.h>
#include <cuda_fp16.h>
#include <cstdint>

#define BATCH 4
#define EDIM 1024
#define CDIM 768
#define TLEN 1024
#define SLEN 1024
#define NH 16
#define DH 64
#define EPSV 1e-5f

// ---------------- scratch (static device globals; no allocation) ----------------
__device__ __half g_wnq[EDIM * EDIM];
__device__ __half g_wnkv[2 * EDIM * CDIM];              // [wnk ; wnv]
__device__ __half g_wno[EDIM * EDIM];
__device__ __half g_xr[BATCH * TLEN * EDIM];            // x^T  [B][T][E] fp16
__device__ __half g_cr[BATCH * SLEN * CDIM];            // ctx^T [B][S][C] fp16
__device__ __half g_q[BATCH * TLEN * EDIM];             // q [B][T][E]
__device__ __half g_k[BATCH * SLEN * EDIM];             // k [B][S][E]
__device__ __half g_v[BATCH * EDIM * SLEN];             // v [B][E][S]
__device__ __half g_p[(long)BATCH * NH * TLEN * SLEN];  // P [b,h][t][s] fp16
__device__ float g_rp[BATCH * NH * SLEN * 8];           // per-t-tile column partials
__device__ float g_r[BATCH * NH * SLEN];                // 1/rowsum (or 0)
__device__ __half g_att[BATCH * TLEN * EDIM];           // att [B][T][E]
__device__ unsigned char g_mask[BATCH * TLEN];
__device__ unsigned char g_mctx[BATCH * SLEN];

__device__ __forceinline__ uint32_t smem_u32(const void* p) {
    uint32_t a;
    asm("{ .reg .u64 t; cvta.to.shared.u64 t, %1; cvt.u32.u64 %0, t; }" : "=r"(a) : "l"(p));
    return a;
}
__device__ __forceinline__ uint32_t packh2(float lo, float hi) {
    __half2 h = __floats2half2_rn(lo, hi);
    return *(uint32_t*)&h;
}
#define CP16(dst, src) asm volatile("cp.async.cg.shared.global [%0], [%1], 16;" :: "r"(dst), "l"(src))
#define CPCOMMIT()     asm volatile("cp.async.commit_group;" ::: "memory")
#define CPWAIT(N)      asm volatile("cp.async.wait_group %0;" :: "n"(N) : "memory")

#define MMA_F16(d, a, b) \
    asm volatile("mma.sync.aligned.m16n8k16.row.col.f32.f16.f16.f32 " \
                 "{%0,%1,%2,%3}, {%4,%5,%6,%7}, {%8,%9}, {%0,%1,%2,%3};" \
                 : "+f"((d)[0]), "+f"((d)[1]), "+f"((d)[2]), "+f"((d)[3]) \
                 : "r"((a)[0]), "r"((a)[1]), "r"((a)[2]), "r"((a)[3]), \
                   "r"((b)[0]), "r"((b)[1]))

#define LDSM4(r0, r1, r2, r3, addr) \
    asm volatile("ldmatrix.sync.aligned.m8n8.x4.shared.b16 {%0,%1,%2,%3}, [%4];" \
                 : "=r"(r0), "=r"(r1), "=r"(r2), "=r"(r3) : "r"(addr))

// ---------------- GEMM parameter set ----------------
struct GP {
    const void* A; int aDiv; long aStrZa, aStrZb; int lda;
    const void* B; int bDiv; long bStrZa, bStrZb; int ldb;
    void* C; int cDiv; long cStrZa, cStrZb; int ldc;
    int K;
    const float* bias; int biasOnM;
    const unsigned char* mask; int maskOnM; int maskDiv; int maskLd;
    const float* res; long resStride;
    float* rp;                       // EPI==3 only: column-partial buffer
};

// ================= fp16 mma GEMM body: BK=64, single-sync pipeline =================
// C[m,n] = sum_k A[m,k] * B[n,k]   (fp16 operands, fp32 accum)
// smem: A [m][k] stride 72, B [n][k] stride 72; fragments via ldmatrix.x4.
// 4 warps; warp tile WM x 64; (BM/WM)*(BN/64) must equal 4.
// EPI 0: conv (bias on m or n; mask->0 on m or n; + residual when CBYTES==4)
// EPI 2: plain fp16 store
// EPI 3: exp-scores (c = mask[m] ? h(expf(c)) : 0) + per-COLUMN partial sums -> rp
template <int EPI, int BM, int BN, int WM, int NS, int CBYTES>
__device__ __forceinline__ void gemm_body(const GP& P, int ytile) {
    constexpr int BK = 64;
    constexpr int STR = BK + 8;             // 72 halves per row
    constexpr int AFL = BM * STR;
    constexpr int BFL = BN * STR;
    constexpr int STG = AFL + BFL;          // halves per stage
    constexpr int NWM = BM / WM;
    constexpr int MF = WM / 16;
    constexpr int NF = 8;

    extern __shared__ char smch[];
    uint32_t sbase = smem_u32(smch);
    int tid = threadIdx.x, wid = tid >> 5, lane = tid & 31;
    int z = blockIdx.z;
    const __half* A = (const __half*)P.A + (z / P.aDiv) * P.aStrZa + (z % P.aDiv) * P.aStrZb;
    const __half* B = (const __half*)P.B + (z / P.bDiv) * P.bStrZa + (z % P.bDiv) * P.bStrZb;
    long mBase = (long)ytile * BM, nBase = (long)blockIdx.x * BN;
    int lda = P.lda, ldb = P.ldb, ldc = P.ldc;

    float acc[MF][NF][4];
#pragma unroll
    for (int i = 0; i < MF; ++i)
#pragma unroll
        for (int j = 0; j < NF; ++j)
#pragma unroll
            for (int t = 0; t < 4; ++t) acc[i][j][t] = 0.f;

    int nIter = P.K / BK;

    auto issue = [&](int stage, int k0) {
        uint32_t aoff = sbase + stage * STG * 2;
#pragma unroll
        for (int r = 0; r < BM / 16; ++r) {       // BM rows x 8 chunks / 128 thr
            int lin = tid + 128 * r;
            int m = lin >> 3, kc = (lin & 7) * 8;
            CP16(aoff + (m * STR + kc) * 2, &A[(mBase + m) * (long)lda + k0 + kc]);
        }
        uint32_t boff = sbase + (stage * STG + AFL) * 2;
#pragma unroll
        for (int r = 0; r < BN / 16; ++r) {
            int lin = tid + 128 * r;
            int n = lin >> 3, kc = (lin & 7) * 8;
            CP16(boff + (n * STR + kc) * 2, &B[(nBase + n) * (long)ldb + k0 + kc]);
        }
    };

    int warpM = wid % NWM, warpN = wid / NWM;
    int mW = warpM * WM, nW = warpN * 64;
    int c4 = lane & 3, r4 = lane >> 2;
    int quad = lane >> 3, lrow = lane & 7;

    // ldmatrix role-based per-thread half-offsets (within a stage)
    uint32_t aRole[MF], bRole[NF / 2];
#pragma unroll
    for (int mf = 0; mf < MF; ++mf)
        aRole[mf] = (uint32_t)((mW + 16 * mf + (quad & 1) * 8 + lrow) * STR + (quad >> 1) * 8);
#pragma unroll
    for (int p = 0; p < NF / 2; ++p)
        bRole[p] = (uint32_t)((nW + 16 * p + (quad >> 1) * 8 + lrow) * STR + (quad & 1) * 8);

    auto compute = [&](int stage) {
        uint32_t As_b = sbase + stage * STG * 2;
        uint32_t Bs_b = As_b + AFL * 2;
#pragma unroll
        for (int kk = 0; kk < BK; kk += 16) {
            uint32_t a[MF][4];
#pragma unroll
            for (int mf = 0; mf < MF; ++mf)
                LDSM4(a[mf][0], a[mf][1], a[mf][2], a[mf][3], As_b + (aRole[mf] + kk) * 2);
            uint32_t b[NF][2];
#pragma unroll
            for (int p = 0; p < NF / 2; ++p)
                LDSM4(b[2 * p][0], b[2 * p][1], b[2 * p + 1][0], b[2 * p + 1][1],
                      Bs_b + (bRole[p] + kk) * 2);
#pragma unroll
            for (int mf = 0; mf < MF; ++mf)
#pragma unroll
                for (int nf = 0; nf < NF; ++nf)
                    MMA_F16(acc[mf][nf], a[mf], b[nf]);
        }
    };

    for (int s = 0; s < NS - 1; ++s) {
        if (s < nIter) issue(s, s * BK);
        CPCOMMIT();
    }
    // single-sync mainloop: top sync of iter it+1 proves all threads finished
    // compute(it) before anyone overwrites stage it%NS.
    for (int it = 0; it < nIter; ++it) {
        CPWAIT(NS - 2);
        __syncthreads();
        compute(it % NS);
        int nx = it + NS - 1;
        if (nx < nIter) issue(nx % NS, nx * BK);
        CPCOMMIT();
    }

    // ---- epilogue ----
    int mb = z / P.maskDiv;
    float bn[NF][2];
    unsigned char mn[NF][2];
    if (EPI == 0) {
#pragma unroll
        for (int nf = 0; nf < NF; ++nf) {
            long n = nBase + nW + nf * 8 + 2 * c4;
            bn[nf][0] = P.biasOnM ? 0.f : P.bias[n];
            bn[nf][1] = P.biasOnM ? 0.f : P.bias[n + 1];
            mn[nf][0] = P.maskOnM ? 1 : P.mask[(long)mb * P.maskLd + n];
            mn[nf][1] = P.maskOnM ? 1 : P.mask[(long)mb * P.maskLd + n + 1];
        }
    }
    float rsumN[NF * 2];
#pragma unroll
    for (int q = 0; q < NF * 2; ++q) rsumN[q] = 0.f;

#pragma unroll
    for (int mf = 0; mf < MF; ++mf) {
#pragma unroll
        for (int half = 0; half < 2; ++half) {
            long m = mBase + mW + mf * 16 + r4 + half * 8;
            float bvm = (EPI == 0 && P.biasOnM) ? P.bias[m] : 0.f;
            bool mOK = true;
            if ((EPI == 0 || EPI == 3) && P.maskOnM)
                mOK = P.mask[(long)mb * P.maskLd + m] != 0;
#pragma unroll
            for (int nf = 0; nf < NF; ++nf) {
                long n = nBase + nW + nf * 8 + 2 * c4;
                float v0 = acc[mf][nf][half * 2 + 0];
                float v1 = acc[mf][nf][half * 2 + 1];
                if (EPI == 0) {
                    if (P.biasOnM) { v0 += bvm; v1 += bvm; }
                    else { v0 += bn[nf][0]; v1 += bn[nf][1]; }
                    if (P.maskOnM) { if (!mOK) { v0 = 0.f; v1 = 0.f; } }
                    else { if (!mn[nf][0]) v0 = 0.f; if (!mn[nf][1]) v1 = 0.f; }
                } else if (EPI == 3) {
                    __half h0 = __float2half_rn(__expf(v0));
                    __half h1 = __float2half_rn(__expf(v1));
                    v0 = mOK ? __half2float(h0) : 0.f;
                    v1 = mOK ? __half2float(h1) : 0.f;
                    rsumN[nf * 2 + 0] += v0;
                    rsumN[nf * 2 + 1] += v1;
                }
                if (CBYTES == 4) {
                    float* Cf = (float*)P.C + (z / P.cDiv) * P.cStrZa + (z % P.cDiv) * P.cStrZb;
                    if (EPI == 0 && P.res) {
                        v0 += P.res[z * P.resStride + m * ldc + n];
                        v1 += P.res[z * P.resStride + m * ldc + n + 1];
                    }
                    float2 o; o.x = v0; o.y = v1;
                    *(float2*)&Cf[m * ldc + n] = o;
                } else {
                    __half* Ch = (__half*)P.C + (z / P.cDiv) * P.cStrZa + (z % P.cDiv) * P.cStrZb;
                    *(uint32_t*)&Ch[m * ldc + n] = packh2(v0, v1);
                }
            }
        }
    }
    if (EPI == 3) {
        // column sums: reduce over r4 lanes (rows), then across warpM warps via smem
#pragma unroll
        for (int q = 0; q < NF * 2; ++q) {
            float v = rsumN[q];
            v += __shfl_xor_sync(0xFFFFFFFFu, v, 4);
            v += __shfl_xor_sync(0xFFFFFFFFu, v, 8);
            v += __shfl_xor_sync(0xFFFFFFFFu, v, 16);
            rsumN[q] = v;
        }
        __syncthreads();
        float* red = (float*)smch;           // [NWM][BN]
        if (r4 == 0) {
#pragma unroll
            for (int nf = 0; nf < NF; ++nf) {
                int nl = nW + nf * 8 + 2 * c4;
                red[warpM * BN + nl] = rsumN[nf * 2 + 0];
                red[warpM * BN + nl + 1] = rsumN[nf * 2 + 1];
            }
        }
        __syncthreads();
        if (tid < BN) {
            float s = red[tid];
#pragma unroll
            for (int w = 1; w < NWM; ++w) s += red[w * BN + tid];
            P.rp[((long)z * SLEN + nBase + tid) * 8 + ytile] = s;
        }
    }
}

// kernel wrapper with uniform triple-param-set dispatch on blockIdx.y
template <int EPI, int BM, int BN, int WM, int NS, int CBYTES>
__global__ __launch_bounds__(128) void mma_gemm(GP p0, GP p1, GP p2, int y1, int y2) {
    int y = blockIdx.y;
    if (y < y1) gemm_body<EPI, BM, BN, WM, NS, CBYTES>(p0, y);
    else if (y < y2) gemm_body<EPI, BM, BN, WM, NS, CBYTES>(p1, y - y1);
    else gemm_body<EPI, BM, BN, WM, NS, CBYTES>(p2, y - y2);
}

// ================= preamble megakernel: canon + transpose x + transpose ctx + ws ======
__device__ void canon_body(const unsigned char* __restrict__ raw,
                           unsigned char* __restrict__ out, int n, int* flag) {
    if (threadIdx.x == 0) *flag = 0;
    __syncthreads();
    int local = 0;
    for (int i = threadIdx.x; i < n; i += 256)
        if ((i & 3) != 0 && raw[i] != 0) local = 1;
    if (local) atomicOr(flag, 1);
    __syncthreads();
    bool is_bool = (*flag != 0);
    for (int i = threadIdx.x; i < n; i += 256)
        out[i] = is_bool ? raw[i] : raw[4 * i];
}

__device__ void transpose_body(const float* __restrict__ in, __half* __restrict__ out,
                               int R, int C, int idx, float* tile /* 32x33 */) {
    int nxb = C / 32;
    int per = nxb * (R / 32);
    int b = idx / per;
    int rem = idx % per;
    int by = rem / nxb, bx = rem % nxb;
    const float* src = in + (long)b * R * C;
    __half* dst = out + (long)b * R * C;
    int c0 = bx * 32, r0 = by * 32;
    int tx = threadIdx.x & 31, ty = threadIdx.x >> 5;   // 32 x 8
#pragma unroll
    for (int i = 0; i < 32; i += 8)
        tile[(ty + i) * 33 + tx] = src[(long)(r0 + ty + i) * C + c0 + tx];
    __syncthreads();
#pragma unroll
    for (int i = 0; i < 32; i += 8)
        dst[(long)(c0 + ty + i) * R + r0 + tx] = __float2half_rn(tile[tx * 33 + ty + i]);
}

__device__ void ws_body(const float* __restrict__ w, __half* __restrict__ outp,
                        int I, int o, float* sh /* >=16 floats */) {
    const float* row = w + (long)o * I;
    float s = 0.f, ss = 0.f;
    for (int i = threadIdx.x; i < I; i += 256) {
        float v = row[i];
        s += v; ss += v * v;
    }
#pragma unroll
    for (int off = 16; off; off >>= 1) {
        s += __shfl_xor_sync(0xFFFFFFFFu, s, off);
        ss += __shfl_xor_sync(0xFFFFFFFFu, ss, off);
    }
    int wid = threadIdx.x >> 5;
    if ((threadIdx.x & 31) == 0) { sh[wid] = s; sh[8 + wid] = ss; }
    __syncthreads();
    if (threadIdx.x == 0) {
        float ts = 0.f, tss = 0.f;
        for (int i = 0; i < 8; i++) { ts += sh[i]; tss += sh[8 + i]; }
        float mu = ts / (float)I;
        float var = tss / (float)I - mu * mu;
        sh[0] = mu; sh[1] = rsqrtf(var + EPSV);
    }
    __syncthreads();
    float mu = sh[0], inv = sh[1];
    for (int i = threadIdx.x; i < I; i += 256)
        outp[(long)o * I + i] = __float2half_rn((row[i] - mu) * inv);
}

#define NB_TX (32 * 32 * BATCH)     // 4096
#define NB_TC (32 * 24 * BATCH)     // 3072
__global__ __launch_bounds__(256) void preamble_kernel(
    const float* __restrict__ x, const float* __restrict__ ctx,
    const unsigned char* __restrict__ mask_raw, const unsigned char* __restrict__ mctx_raw,
    const float* __restrict__ qw, const float* __restrict__ kw,
    const float* __restrict__ vw, const float* __restrict__ ow,
    __half* __restrict__ xr, __half* __restrict__ cr,
    unsigned char* __restrict__ mask, unsigned char* __restrict__ mctx,
    __half* __restrict__ wnq, __half* __restrict__ wnkv, __half* __restrict__ wno)
{
    __shared__ float shm[32 * 33];
    int b = blockIdx.x;
    if (b < 2) {
        canon_body(b ? mctx_raw : mask_raw, b ? mctx : mask, BATCH * TLEN, (int*)shm);
    } else if (b < 2 + NB_TX) {
        transpose_body(x, xr, EDIM, TLEN, b - 2, shm);
    } else if (b < 2 + NB_TX + NB_TC) {
        transpose_body(ctx, cr, CDIM, SLEN, b - 2 - NB_TX, shm);
    } else {
        int idx = b - 2 - NB_TX - NB_TC;
        int c = idx >> 10, o = idx & 1023;
        const float* w; __half* outp; int I;
        if (c == 0) { w = qw; outp = wnq; I = EDIM; }
        else if (c == 1) { w = kw; outp = wnkv; I = CDIM; }
        else if (c == 2) { w = vw; outp = wnkv + EDIM * CDIM; I = CDIM; }
        else { w = ow; outp = wno; I = EDIM; }
        ws_body(w, outp, I, o, shm);
    }
}

// ---------------- per-head LayerNorm over dh=64 ----------------
// c=0: q [B][T][E] contiguous dh (scale 1/256); c=1: k [B][S][E]; c=2: v [B][E][S] strided
__global__ void ln_kernel(__half* __restrict__ qbuf, __half* __restrict__ kbuf,
                          __half* __restrict__ vbuf,
                          const float* __restrict__ gq, const float* __restrict__ bq,
                          const float* __restrict__ gk, const float* __restrict__ bk,
                          const float* __restrict__ gv, const float* __restrict__ bv) {
    int c = blockIdx.y / (BATCH * NH);
    int bh = blockIdx.y % (BATCH * NH);
    int b = bh / NH, h = bh % NH;
    int l = blockIdx.x * blockDim.x + threadIdx.x;
    float vals[DH];
    float s = 0.f, ss = 0.f;
    if (c < 2) {
        __half* base = (c == 0 ? qbuf : kbuf) + ((long)b * TLEN + l) * EDIM + h * DH;
        const float* g = c == 0 ? gq : gk;
        const float* bt = c == 0 ? bq : bk;
        float scale = c == 0 ? (1.f / 256.f) : 1.f;
#pragma unroll
        for (int i = 0; i < 8; ++i) {
            uint4 u = ((const uint4*)base)[i];
            const __half2* hp = (const __half2*)&u;
#pragma unroll
            for (int j = 0; j < 4; ++j) {
                float2 f = __half22float2(hp[j]);
                vals[i * 8 + j * 2] = f.x;
                vals[i * 8 + j * 2 + 1] = f.y;
                s += f.x + f.y;
                ss += f.x * f.x + f.y * f.y;
            }
        }
        float mu = s * (1.f / DH);
        float var = ss * (1.f / DH) - mu * mu;
        float inv = rsqrtf(var + EPSV);
#pragma unroll
        for (int i = 0; i < 8; ++i) {
            uint4 u;
            uint32_t* up = (uint32_t*)&u;
#pragma unroll
            for (int j = 0; j < 4; ++j) {
                int d0 = i * 8 + j * 2;
                up[j] = packh2(((vals[d0] - mu) * inv * g[d0] + bt[d0]) * scale,
                               ((vals[d0 + 1] - mu) * inv * g[d0 + 1] + bt[d0 + 1]) * scale);
            }
            ((uint4*)base)[i] = u;
        }
    } else {
        __half* base = vbuf + (long)b * EDIM * SLEN + (long)h * DH * SLEN + l;
#pragma unroll
        for (int d = 0; d < DH; d++) {
            float v = __half2float(base[(long)d * SLEN]);
            vals[d] = v;
            s += v; ss += v * v;
        }
        float mu = s * (1.f / DH);
        float var = ss * (1.f / DH) - mu * mu;
        float inv = rsqrtf(var + EPSV);
#pragma unroll
        for (int d = 0; d < DH; d++)
            base[(long)d * SLEN] = __float2half_rn((vals[d] - mu) * inv * gv[d] + bv[d]);
    }
}

// ---------------- finalize r: r[i] = mctx && sum>0 ? 1/sum(rp[i][0..7]) : 0 ----------------
__global__ void finalize_r(const float* __restrict__ rp, float* __restrict__ r,
                           const unsigned char* __restrict__ mctx) {
    int i = blockIdx.x * blockDim.x + threadIdx.x;     // 0..65535
    float4 a = ((const float4*)rp)[i * 2];
    float4 b = ((const float4*)rp)[i * 2 + 1];
    float s = ((a.x + a.y) + (a.z + a.w)) + ((b.x + b.y) + (b.z + b.w));
    int bidx = i >> 14, sidx = i & (SLEN - 1);
    r[i] = (mctx[bidx * SLEN + sidx] && s > 0.f) ? (1.f / s) : 0.f;
}

// ---------------- v' = h(v * r[b,h,s]) in-place (fp16) ----------------
__global__ void vscale_kernel(__half* __restrict__ vbuf, const float* __restrict__ r) {
    long i = (long)blockIdx.x * blockDim.x + threadIdx.x;   // 4-half groups over [B][E][S]
    long fi = i * 4;
    int b = (int)(fi / ((long)EDIM * SLEN));
    long rem = fi % ((long)EDIM * SLEN);
    int e = (int)(rem / SLEN), s = (int)(rem % SLEN);
    int h = e / DH;
    __half* vp = vbuf + (long)b * EDIM * SLEN + (long)e * SLEN + s;
    float4 rv = *(const float4*)&r[((long)b * NH + h) * SLEN + s];
    uint2 v = *(uint2*)vp;
    __half2 v01 = *(__half2*)&v.x, v23 = *(__half2*)&v.y;
    uint2 o;
    o.x = packh2(__half2float(v01.x) * rv.x, __half2float(v01.y) * rv.y);
    o.y = packh2(__half2float(v23.x) * rv.z, __half2float(v23.y) * rv.w);
    *(uint2*)vp = o;
}

// ---------------- launch ----------------
extern "C" void kernel_launch(void* const* d_in, const int* in_sizes, int n_in,
                              void* d_out, int out_size) {
    const float* x = (const float*)d_in[0];
    const float* ctx = (const float*)d_in[1];
    const unsigned char* mask_raw = (const unsigned char*)d_in[2];
    const unsigned char* mctx_raw = (const unsigned char*)d_in[3];
    const float* qw = (const float*)d_in[4];
    const float* qb = (const float*)d_in[5];
    const float* kw = (const float*)d_in[6];
    const float* kb = (const float*)d_in[7];
    const float* vw = (const float*)d_in[8];
    const float* vb = (const float*)d_in[9];
    const float* ow = (const float*)d_in[10];
    const float* ob = (const float*)d_in[11];
    const float* gq = (const float*)d_in[12];
    const float* bq = (const float*)d_in[13];
    const float* gk = (const float*)d_in[14];
    const float* bk = (const float*)d_in[15];
    const float* gv = (const float*)d_in[16];
    const float* bv = (const float*)d_in[17];
    float* out = (float*)d_out;

    __half *wnq, *wnkv, *wno, *xr, *cr, *qbuf, *kbuf, *vbuf, *pbuf, *abuf;
    float *rpbuf, *rbuf;
    unsigned char *mask, *mctx;
    cudaGetSymbolAddress((void**)&wnq, g_wnq);
    cudaGetSymbolAddress((void**)&wnkv, g_wnkv);
    cudaGetSymbolAddress((void**)&wno, g_wno);
    cudaGetSymbolAddress((void**)&xr, g_xr);
    cudaGetSymbolAddress((void**)&cr, g_cr);
    cudaGetSymbolAddress((void**)&qbuf, g_q);
    cudaGetSymbolAddress((void**)&kbuf, g_k);
    cudaGetSymbolAddress((void**)&vbuf, g_v);
    cudaGetSymbolAddress((void**)&pbuf, g_p);
    cudaGetSymbolAddress((void**)&rpbuf, g_rp);
    cudaGetSymbolAddress((void**)&rbuf, g_r);
    cudaGetSymbolAddress((void**)&abuf, g_att);
    cudaGetSymbolAddress((void**)&mask, g_mask);
    cudaGetSymbolAddress((void**)&mctx, g_mctx);

    __half* wnk = wnkv;
    __half* wnv = wnkv + EDIM * CDIM;

    const int SM_PROJ = 3 * (128 + 128) * 72 * 2;   // 110592, NS=3
    const int SM_SC = 2 * (128 + 64) * 72 * 2;      // 55296,  NS=2, BN=64
    const int SM_AV = 2 * (256 + 64) * 72 * 2;      // 92160,  NS=2
    const int SM_OP = 3 * (128 + 128) * 72 * 2;     // 110592, NS=3
    cudaFuncSetAttribute((const void*)mma_gemm<0, 128, 128, 64, 3, 2>,
                         cudaFuncAttributeMaxDynamicSharedMemorySize, SM_PROJ);
    cudaFuncSetAttribute((const void*)mma_gemm<3, 128, 64, 32, 2, 2>,
                         cudaFuncAttributeMaxDynamicSharedMemorySize, SM_SC);
    cudaFuncSetAttribute((const void*)mma_gemm<2, 256, 64, 64, 2, 2>,
                         cudaFuncAttributeMaxDynamicSharedMemorySize, SM_AV);
    cudaFuncSetAttribute((const void*)mma_gemm<0, 128, 128, 64, 3, 4>,
                         cudaFuncAttributeMaxDynamicSharedMemorySize, SM_OP);

    // 0+1. preamble: canon masks + transpose/round x,ctx + weight standardization
    preamble_kernel<<<2 + NB_TX + NB_TC + 4 * EDIM, 256>>>(
        x, ctx, mask_raw, mctx_raw, qw, kw, vw, ow,
        xr, cr, mask, mctx, wnq, wnkv, wno);

    // 2. merged Q + K + V projections: one launch, y-dispatch 8|8|8
    GP pQ = { xr, 1, (long)TLEN * EDIM, 0, EDIM,
              wnq, 1, 0, 0, EDIM,
              qbuf, 1, (long)TLEN * EDIM, 0, EDIM,
              EDIM, qb, 0, mask, 1, 1, TLEN, nullptr, 0, nullptr };
    GP pK = { cr, 1, (long)SLEN * CDIM, 0, CDIM,
              wnk, 1, 0, 0, CDIM,
              kbuf, 1, (long)SLEN * EDIM, 0, EDIM,
              CDIM, kb, 0, mctx, 1, 1, SLEN, nullptr, 0, nullptr };
    GP pV = { wnv, 1, 0, 0, CDIM,
              cr, 1, (long)SLEN * CDIM, 0, CDIM,
              vbuf, 1, (long)EDIM * SLEN, 0, SLEN,
              CDIM, vb, 1, mctx, 0, 1, SLEN, nullptr, 0, nullptr };
    mma_gemm<0, 128, 128, 64, 3, 2><<<dim3(8, 24, BATCH), 128, SM_PROJ>>>(pQ, pK, pV, 8, 16);

    // 3. per-head LayerNorm over dh (q scaled by 1/256)
    ln_kernel<<<dim3(TLEN / 128, 3 * BATCH * NH), 128>>>(qbuf, kbuf, vbuf,
                                                         gq, bq, gk, bk, gv, bv);

    // 4. P[t,s] = mask[t] ? exp(sum_d q'[t,d] k[s,d]) : 0, + column partials -> rp
    //    BM=128 (t), BN=64 (s), WM=32: acc halved -> 4 CTAs/SM, 8192 CTAs
    GP pS = { qbuf, NH, (long)TLEN * EDIM, DH, EDIM,
              kbuf, NH, (long)SLEN * EDIM, DH, EDIM,
              pbuf, 1, (long)TLEN * SLEN, 0, SLEN,
              DH, nullptr, 0, mask, 1, NH, TLEN, nullptr, 0, rpbuf };
    mma_gemm<3, 128, 64, 32, 2, 2><<<dim3(SLEN / 64, TLEN / 128, BATCH * NH), 128, SM_SC>>>(
        pS, pS, pS, 1 << 30, 1 << 30);

    // 5. finalize r; v' = v * r
    finalize_r<<<BATCH * NH * SLEN / 256, 256>>>(rpbuf, rbuf, mctx);
    vscale_kernel<<<BATCH * EDIM * SLEN / 4 / 256, 256>>>(vbuf, rbuf);

    // 6. att[t,d] = sum_s P[t,s] v'[d,s]  -> att [B][T][E] (256x64 tiles, R12 config)
    GP pA = { pbuf, 1, (long)TLEN * SLEN, 0, SLEN,
              vbuf, NH, (long)EDIM * SLEN, (long)DH * SLEN, SLEN,
              abuf, NH, (long)TLEN * EDIM, DH, EDIM,
              SLEN, nullptr, 0, mask, 1, 1, TLEN, nullptr, 0, nullptr };
    mma_gemm<2, 256, 64, 64, 2, 2><<<dim3(1, TLEN / 256, BATCH * NH), 128, SM_AV>>>(
        pA, pA, pA, 1 << 30, 1 << 30);

    // 7. out[e,t] = sum_e' wno[e,e'] att[t,e'] + ob + mask + x
    GP pO = { wno, 1, 0, 0, EDIM,
              abuf, 1, (long)TLEN * EDIM, 0, EDIM,
              out, 1, (long)EDIM * TLEN, 0, TLEN,
              EDIM, ob, 1, mask, 0, 1, TLEN, x, (long)EDIM * TLEN, nullptr };
    mma_gemm<0, 128, 128, 64, 3, 4><<<dim3(TLEN / 128, EDIM / 128, BATCH), 128, SM_OP>>>(
        pO, pO, pO, 1 << 30, 1 << 30);
}

// round 16
// speedup vs baseline: 1.0413x; 1.0133x over previous
#include <cuda_runtime.h>
#include <cuda_fp16.h>
#include <cstdint>

#define BATCH 4
#define EDIM 1024
#define CDIM 768
#define TLEN 1024
#define SLEN 1024
#define NH 16
#define DH 64
#define EPSV 1e-5f

// ---------------- scratch (static device globals; no allocation) ----------------
__device__ __half g_wnq[EDIM * EDIM];
__device__ __half g_wnkv[2 * EDIM * CDIM];              // [wnk ; wnv]
__device__ __half g_wno[EDIM * EDIM];
__device__ __half g_xr[BATCH * TLEN * EDIM];            // x^T  [B][T][E] fp16
__device__ __half g_cr[BATCH * SLEN * CDIM];            // ctx^T [B][S][C] fp16
__device__ __half g_q[BATCH * TLEN * EDIM];             // q [B][T][E]
__device__ __half g_k[BATCH * SLEN * EDIM];             // k [B][S][E]
__device__ __half g_v[BATCH * EDIM * SLEN];             // v [B][E][S]
__device__ __half g_p[(long)BATCH * NH * TLEN * SLEN];  // P [b,h][t][s] fp16
__device__ float g_rp[BATCH * NH * SLEN * 8];           // per-t-tile column partials
__device__ float g_r[BATCH * NH * SLEN];                // 1/rowsum (or 0)
__device__ __half g_att[BATCH * TLEN * EDIM];           // att [B][T][E]
__device__ unsigned char g_mask[BATCH * TLEN];
__device__ unsigned char g_mctx[BATCH * SLEN];

__device__ __forceinline__ uint32_t smem_u32(const void* p) {
    uint32_t a;
    asm("{ .reg .u64 t; cvta.to.shared.u64 t, %1; cvt.u32.u64 %0, t; }" : "=r"(a) : "l"(p));
    return a;
}
__device__ __forceinline__ uint32_t packh2(float lo, float hi) {
    __half2 h = __floats2half2_rn(lo, hi);
    return *(uint32_t*)&h;
}
#define CP16(dst, src) asm volatile("cp.async.cg.shared.global [%0], [%1], 16;" :: "r"(dst), "l"(src))
#define CPCOMMIT()     asm volatile("cp.async.commit_group;" ::: "memory")
#define CPWAIT(N)      asm volatile("cp.async.wait_group %0;" :: "n"(N) : "memory")

#define MMA_F16(d, a, b) \
    asm volatile("mma.sync.aligned.m16n8k16.row.col.f32.f16.f16.f32 " \
                 "{%0,%1,%2,%3}, {%4,%5,%6,%7}, {%8,%9}, {%0,%1,%2,%3};" \
                 : "+f"((d)[0]), "+f"((d)[1]), "+f"((d)[2]), "+f"((d)[3]) \
                 : "r"((a)[0]), "r"((a)[1]), "r"((a)[2]), "r"((a)[3]), \
                   "r"((b)[0]), "r"((b)[1]))

#define LDSM4(r0, r1, r2, r3, addr) \
    asm volatile("ldmatrix.sync.aligned.m8n8.x4.shared.b16 {%0,%1,%2,%3}, [%4];" \
                 : "=r"(r0), "=r"(r1), "=r"(r2), "=r"(r3) : "r"(addr))

// ---------------- GEMM parameter set ----------------
struct GP {
    const void* A; int aDiv; long aStrZa, aStrZb; int lda;
    const void* B; int bDiv; long bStrZa, bStrZb; int ldb;
    void* C; int cDiv; long cStrZa, cStrZb; int ldc;
    int K;
    const float* bias; int biasOnM;
    const unsigned char* mask; int maskOnM; int maskDiv; int maskLd;
    const float* res; long resStride;
    float* rp;                       // EPI==3 only: column-partial buffer
};

// ================= fp16 mma GEMM body: BK=64, single-sync pipeline =================
// C[m,n] = sum_k A[m,k] * B[n,k]   (fp16 operands, fp32 accum)
// smem: A [m][k] stride 72, B [n][k] stride 72; fragments via ldmatrix.x4.
// NT threads (NT/32 warps); warp tile WM x 64; (BM/WM)*(BN/64) must equal NT/32.
// EPI 0: conv (bias on m or n; mask->0 on m or n; + residual when CBYTES==4)
// EPI 2: plain fp16 store
// EPI 3: exp-scores (c = mask[m] ? h(expf(c)) : 0) + per-COLUMN partial sums -> rp
template <int EPI, int BM, int BN, int WM, int NS, int CBYTES, int NT>
__device__ __forceinline__ void gemm_body(const GP& P, int ytile) {
    constexpr int BK = 64;
    constexpr int STR = BK + 8;             // 72 halves per row
    constexpr int AFL = BM * STR;
    constexpr int BFL = BN * STR;
    constexpr int STG = AFL + BFL;          // halves per stage
    constexpr int NWM = BM / WM;
    constexpr int MF = WM / 16;
    constexpr int NF = 8;

    extern __shared__ char smch[];
    uint32_t sbase = smem_u32(smch);
    int tid = threadIdx.x, wid = tid >> 5, lane = tid & 31;
    int z = blockIdx.z;
    const __half* A = (const __half*)P.A + (z / P.aDiv) * P.aStrZa + (z % P.aDiv) * P.aStrZb;
    const __half* B = (const __half*)P.B + (z / P.bDiv) * P.bStrZa + (z % P.bDiv) * P.bStrZb;
    long mBase = (long)ytile * BM, nBase = (long)blockIdx.x * BN;
    int lda = P.lda, ldb = P.ldb, ldc = P.ldc;

    float acc[MF][NF][4];
#pragma unroll
    for (int i = 0; i < MF; ++i)
#pragma unroll
        for (int j = 0; j < NF; ++j)
#pragma unroll
            for (int t = 0; t < 4; ++t) acc[i][j][t] = 0.f;

    int nIter = P.K / BK;

    auto issue = [&](int stage, int k0) {
        uint32_t aoff = sbase + stage * STG * 2;
#pragma unroll
        for (int r = 0; r < BM * 8 / NT; ++r) {   // BM rows x 8 chunks / NT thr
            int lin = tid + NT * r;
            int m = lin >> 3, kc = (lin & 7) * 8;
            CP16(aoff + (m * STR + kc) * 2, &A[(mBase + m) * (long)lda + k0 + kc]);
        }
        uint32_t boff = sbase + (stage * STG + AFL) * 2;
#pragma unroll
        for (int r = 0; r < BN * 8 / NT; ++r) {
            int lin = tid + NT * r;
            int n = lin >> 3, kc = (lin & 7) * 8;
            CP16(boff + (n * STR + kc) * 2, &B[(nBase + n) * (long)ldb + k0 + kc]);
        }
    };

    int warpM = wid % NWM, warpN = wid / NWM;
    int mW = warpM * WM, nW = warpN * 64;
    int c4 = lane & 3, r4 = lane >> 2;
    int quad = lane >> 3, lrow = lane & 7;

    // ldmatrix role-based per-thread half-offsets (within a stage)
    uint32_t aRole[MF], bRole[NF / 2];
#pragma unroll
    for (int mf = 0; mf < MF; ++mf)
        aRole[mf] = (uint32_t)((mW + 16 * mf + (quad & 1) * 8 + lrow) * STR + (quad >> 1) * 8);
#pragma unroll
    for (int p = 0; p < NF / 2; ++p)
        bRole[p] = (uint32_t)((nW + 16 * p + (quad >> 1) * 8 + lrow) * STR + (quad & 1) * 8);

    auto compute = [&](int stage) {
        uint32_t As_b = sbase + stage * STG * 2;
        uint32_t Bs_b = As_b + AFL * 2;
#pragma unroll
        for (int kk = 0; kk < BK; kk += 16) {
            uint32_t a[MF][4];
#pragma unroll
            for (int mf = 0; mf < MF; ++mf)
                LDSM4(a[mf][0], a[mf][1], a[mf][2], a[mf][3], As_b + (aRole[mf] + kk) * 2);
            uint32_t b[NF][2];
#pragma unroll
            for (int p = 0; p < NF / 2; ++p)
                LDSM4(b[2 * p][0], b[2 * p][1], b[2 * p + 1][0], b[2 * p + 1][1],
                      Bs_b + (bRole[p] + kk) * 2);
#pragma unroll
            for (int mf = 0; mf < MF; ++mf)
#pragma unroll
                for (int nf = 0; nf < NF; ++nf)
                    MMA_F16(acc[mf][nf], a[mf], b[nf]);
        }
    };

    for (int s = 0; s < NS - 1; ++s) {
        if (s < nIter) issue(s, s * BK);
        CPCOMMIT();
    }
    // single-sync mainloop: top sync of iter it+1 proves all threads finished
    // compute(it) before anyone overwrites stage it%NS.
    for (int it = 0; it < nIter; ++it) {
        CPWAIT(NS - 2);
        __syncthreads();
        compute(it % NS);
        int nx = it + NS - 1;
        if (nx < nIter) issue(nx % NS, nx * BK);
        CPCOMMIT();
    }

    // ---- epilogue ----
    int mb = z / P.maskDiv;
    float bn[NF][2];
    unsigned char mn[NF][2];
    if (EPI == 0) {
#pragma unroll
        for (int nf = 0; nf < NF; ++nf) {
            long n = nBase + nW + nf * 8 + 2 * c4;
            bn[nf][0] = P.biasOnM ? 0.f : P.bias[n];
            bn[nf][1] = P.biasOnM ? 0.f : P.bias[n + 1];
            mn[nf][0] = P.maskOnM ? 1 : P.mask[(long)mb * P.maskLd + n];
            mn[nf][1] = P.maskOnM ? 1 : P.mask[(long)mb * P.maskLd + n + 1];
        }
    }
    float rsumN[NF * 2];
#pragma unroll
    for (int q = 0; q < NF * 2; ++q) rsumN[q] = 0.f;

#pragma unroll
    for (int mf = 0; mf < MF; ++mf) {
#pragma unroll
        for (int half = 0; half < 2; ++half) {
            long m = mBase + mW + mf * 16 + r4 + half * 8;
            float bvm = (EPI == 0 && P.biasOnM) ? P.bias[m] : 0.f;
            bool mOK = true;
            if ((EPI == 0 || EPI == 3) && P.maskOnM)
                mOK = P.mask[(long)mb * P.maskLd + m] != 0;
#pragma unroll
            for (int nf = 0; nf < NF; ++nf) {
                long n = nBase + nW + nf * 8 + 2 * c4;
                float v0 = acc[mf][nf][half * 2 + 0];
                float v1 = acc[mf][nf][half * 2 + 1];
                if (EPI == 0) {
                    if (P.biasOnM) { v0 += bvm; v1 += bvm; }
                    else { v0 += bn[nf][0]; v1 += bn[nf][1]; }
                    if (P.maskOnM) { if (!mOK) { v0 = 0.f; v1 = 0.f; } }
                    else { if (!mn[nf][0]) v0 = 0.f; if (!mn[nf][1]) v1 = 0.f; }
                } else if (EPI == 3) {
                    __half h0 = __float2half_rn(__expf(v0));
                    __half h1 = __float2half_rn(__expf(v1));
                    v0 = mOK ? __half2float(h0) : 0.f;
                    v1 = mOK ? __half2float(h1) : 0.f;
                    rsumN[nf * 2 + 0] += v0;
                    rsumN[nf * 2 + 1] += v1;
                }
                if (CBYTES == 4) {
                    float* Cf = (float*)P.C + (z / P.cDiv) * P.cStrZa + (z % P.cDiv) * P.cStrZb;
                    if (EPI == 0 && P.res) {
                        v0 += P.res[z * P.resStride + m * ldc + n];
                        v1 += P.res[z * P.resStride + m * ldc + n + 1];
                    }
                    float2 o; o.x = v0; o.y = v1;
                    *(float2*)&Cf[m * ldc + n] = o;
                } else {
                    __half* Ch = (__half*)P.C + (z / P.cDiv) * P.cStrZa + (z % P.cDiv) * P.cStrZb;
                    *(uint32_t*)&Ch[m * ldc + n] = packh2(v0, v1);
                }
            }
        }
    }
    if (EPI == 3) {
        // column sums: reduce over r4 lanes (rows), then across warpM warps via smem
#pragma unroll
        for (int q = 0; q < NF * 2; ++q) {
            float v = rsumN[q];
            v += __shfl_xor_sync(0xFFFFFFFFu, v, 4);
            v += __shfl_xor_sync(0xFFFFFFFFu, v, 8);
            v += __shfl_xor_sync(0xFFFFFFFFu, v, 16);
            rsumN[q] = v;
        }
        __syncthreads();
        float* red = (float*)smch;           // [NWM][BN]
        if (r4 == 0) {
#pragma unroll
            for (int nf = 0; nf < NF; ++nf) {
                int nl = nW + nf * 8 + 2 * c4;
                red[warpM * BN + nl] = rsumN[nf * 2 + 0];
                red[warpM * BN + nl + 1] = rsumN[nf * 2 + 1];
            }
        }
        __syncthreads();
        if (tid < BN) {
            float s = red[tid];
#pragma unroll
            for (int w = 1; w < NWM; ++w) s += red[w * BN + tid];
            P.rp[((long)z * SLEN + nBase + tid) * 8 + ytile] = s;
        }
    }
}

// kernel wrapper with uniform triple-param-set dispatch on blockIdx.y
template <int EPI, int BM, int BN, int WM, int NS, int CBYTES, int NT>
__global__ __launch_bounds__(NT) void mma_gemm(GP p0, GP p1, GP p2, int y1, int y2) {
    int y = blockIdx.y;
    if (y < y1) gemm_body<EPI, BM, BN, WM, NS, CBYTES, NT>(p0, y);
    else if (y < y2) gemm_body<EPI, BM, BN, WM, NS, CBYTES, NT>(p1, y - y1);
    else gemm_body<EPI, BM, BN, WM, NS, CBYTES, NT>(p2, y - y2);
}

// ================= preamble megakernel: canon + transpose x + transpose ctx + ws ======
__device__ void canon_body(const unsigned char* __restrict__ raw,
                           unsigned char* __restrict__ out, int n, int* flag) {
    if (threadIdx.x == 0) *flag = 0;
    __syncthreads();
    int local = 0;
    for (int i = threadIdx.x; i < n; i += 256)
        if ((i & 3) != 0 && raw[i] != 0) local = 1;
    if (local) atomicOr(flag, 1);
    __syncthreads();
    bool is_bool = (*flag != 0);
    for (int i = threadIdx.x; i < n; i += 256)
        out[i] = is_bool ? raw[i] : raw[4 * i];
}

__device__ void transpose_body(const float* __restrict__ in, __half* __restrict__ out,
                               int R, int C, int idx, float* tile /* 32x33 */) {
    int nxb = C / 32;
    int per = nxb * (R / 32);
    int b = idx / per;
    int rem = idx % per;
    int by = rem / nxb, bx = rem % nxb;
    const float* src = in + (long)b * R * C;
    __half* dst = out + (long)b * R * C;
    int c0 = bx * 32, r0 = by * 32;
    int tx = threadIdx.x & 31, ty = threadIdx.x >> 5;   // 32 x 8
#pragma unroll
    for (int i = 0; i < 32; i += 8)
        tile[(ty + i) * 33 + tx] = src[(long)(r0 + ty + i) * C + c0 + tx];
    __syncthreads();
#pragma unroll
    for (int i = 0; i < 32; i += 8)
        dst[(long)(c0 + ty + i) * R + r0 + tx] = __float2half_rn(tile[tx * 33 + ty + i]);
}

__device__ void ws_body(const float* __restrict__ w, __half* __restrict__ outp,
                        int I, int o, float* sh /* >=16 floats */) {
    const float* row = w + (long)o * I;
    float s = 0.f, ss = 0.f;
    for (int i = threadIdx.x; i < I; i += 256) {
        float v = row[i];
        s += v; ss += v * v;
    }
#pragma unroll
    for (int off = 16; off; off >>= 1) {
        s += __shfl_xor_sync(0xFFFFFFFFu, s, off);
        ss += __shfl_xor_sync(0xFFFFFFFFu, ss, off);
    }
    int wid = threadIdx.x >> 5;
    if ((threadIdx.x & 31) == 0) { sh[wid] = s; sh[8 + wid] = ss; }
    __syncthreads();
    if (threadIdx.x == 0) {
        float ts = 0.f, tss = 0.f;
        for (int i = 0; i < 8; i++) { ts += sh[i]; tss += sh[8 + i]; }
        float mu = ts / (float)I;
        float var = tss / (float)I - mu * mu;
        sh[0] = mu; sh[1] = rsqrtf(var + EPSV);
    }
    __syncthreads();
    float mu = sh[0], inv = sh[1];
    for (int i = threadIdx.x; i < I; i += 256)
        outp[(long)o * I + i] = __float2half_rn((row[i] - mu) * inv);
}

#define NB_TX (32 * 32 * BATCH)     // 4096
#define NB_TC (32 * 24 * BATCH)     // 3072
__global__ __launch_bounds__(256) void preamble_kernel(
    const float* __restrict__ x, const float* __restrict__ ctx,
    const unsigned char* __restrict__ mask_raw, const unsigned char* __restrict__ mctx_raw,
    const float* __restrict__ qw, const float* __restrict__ kw,
    const float* __restrict__ vw, const float* __restrict__ ow,
    __half* __restrict__ xr, __half* __restrict__ cr,
    unsigned char* __restrict__ mask, unsigned char* __restrict__ mctx,
    __half* __restrict__ wnq, __half* __restrict__ wnkv, __half* __restrict__ wno)
{
    __shared__ float shm[32 * 33];
    int b = blockIdx.x;
    if (b < 2) {
        canon_body(b ? mctx_raw : mask_raw, b ? mctx : mask, BATCH * TLEN, (int*)shm);
    } else if (b < 2 + NB_TX) {
        transpose_body(x, xr, EDIM, TLEN, b - 2, shm);
    } else if (b < 2 + NB_TX + NB_TC) {
        transpose_body(ctx, cr, CDIM, SLEN, b - 2 - NB_TX, shm);
    } else {
        int idx = b - 2 - NB_TX - NB_TC;
        int c = idx >> 10, o = idx & 1023;
        const float* w; __half* outp; int I;
        if (c == 0) { w = qw; outp = wnq; I = EDIM; }
        else if (c == 1) { w = kw; outp = wnkv; I = CDIM; }
        else if (c == 2) { w = vw; outp = wnkv + EDIM * CDIM; I = CDIM; }
        else { w = ow; outp = wno; I = EDIM; }
        ws_body(w, outp, I, o, shm);
    }
}

// ---------------- per-head LayerNorm over dh=64 ----------------
// c=0: q [B][T][E] contiguous dh (scale 1/256); c=1: k [B][S][E]; c=2: v [B][E][S] strided
__global__ void ln_kernel(__half* __restrict__ qbuf, __half* __restrict__ kbuf,
                          __half* __restrict__ vbuf,
                          const float* __restrict__ gq, const float* __restrict__ bq,
                          const float* __restrict__ gk, const float* __restrict__ bk,
                          const float* __restrict__ gv, const float* __restrict__ bv) {
    int c = blockIdx.y / (BATCH * NH);
    int bh = blockIdx.y % (BATCH * NH);
    int b = bh / NH, h = bh % NH;
    int l = blockIdx.x * blockDim.x + threadIdx.x;
    float vals[DH];
    float s = 0.f, ss = 0.f;
    if (c < 2) {
        __half* base = (c == 0 ? qbuf : kbuf) + ((long)b * TLEN + l) * EDIM + h * DH;
        const float* g = c == 0 ? gq : gk;
        const float* bt = c == 0 ? bq : bk;
        float scale = c == 0 ? (1.f / 256.f) : 1.f;
#pragma unroll
        for (int i = 0; i < 8; ++i) {
            uint4 u = ((const uint4*)base)[i];
            const __half2* hp = (const __half2*)&u;
#pragma unroll
            for (int j = 0; j < 4; ++j) {
                float2 f = __half22float2(hp[j]);
                vals[i * 8 + j * 2] = f.x;
                vals[i * 8 + j * 2 + 1] = f.y;
                s += f.x + f.y;
                ss += f.x * f.x + f.y * f.y;
            }
        }
        float mu = s * (1.f / DH);
        float var = ss * (1.f / DH) - mu * mu;
        float inv = rsqrtf(var + EPSV);
#pragma unroll
        for (int i = 0; i < 8; ++i) {
            uint4 u;
            uint32_t* up = (uint32_t*)&u;
#pragma unroll
            for (int j = 0; j < 4; ++j) {
                int d0 = i * 8 + j * 2;
                up[j] = packh2(((vals[d0] - mu) * inv * g[d0] + bt[d0]) * scale,
                               ((vals[d0 + 1] - mu) * inv * g[d0 + 1] + bt[d0 + 1]) * scale);
            }
            ((uint4*)base)[i] = u;
        }
    } else {
        __half* base = vbuf + (long)b * EDIM * SLEN + (long)h * DH * SLEN + l;
#pragma unroll
        for (int d = 0; d < DH; d++) {
            float v = __half2float(base[(long)d * SLEN]);
            vals[d] = v;
            s += v; ss += v * v;
        }
        float mu = s * (1.f / DH);
        float var = ss * (1.f / DH) - mu * mu;
        float inv = rsqrtf(var + EPSV);
#pragma unroll
        for (int d = 0; d < DH; d++)
            base[(long)d * SLEN] = __float2half_rn((vals[d] - mu) * inv * gv[d] + bv[d]);
    }
}

// ---------------- finalize r: r[i] = mctx && sum>0 ? 1/sum(rp[i][0..7]) : 0 ----------------
__global__ void finalize_r(const float* __restrict__ rp, float* __restrict__ r,
                           const unsigned char* __restrict__ mctx) {
    int i = blockIdx.x * blockDim.x + threadIdx.x;     // 0..65535
    float4 a = ((const float4*)rp)[i * 2];
    float4 b = ((const float4*)rp)[i * 2 + 1];
    float s = ((a.x + a.y) + (a.z + a.w)) + ((b.x + b.y) + (b.z + b.w));
    int bidx = i >> 14, sidx = i & (SLEN - 1);
    r[i] = (mctx[bidx * SLEN + sidx] && s > 0.f) ? (1.f / s) : 0.f;
}

// ---------------- v' = h(v * r[b,h,s]) in-place (fp16) ----------------
__global__ void vscale_kernel(__half* __restrict__ vbuf, const float* __restrict__ r) {
    long i = (long)blockIdx.x * blockDim.x + threadIdx.x;   // 4-half groups over [B][E][S]
    long fi = i * 4;
    int b = (int)(fi / ((long)EDIM * SLEN));
    long rem = fi % ((long)EDIM * SLEN);
    int e = (int)(rem / SLEN), s = (int)(rem % SLEN);
    int h = e / DH;
    __half* vp = vbuf + (long)b * EDIM * SLEN + (long)e * SLEN + s;
    float4 rv = *(const float4*)&r[((long)b * NH + h) * SLEN + s];
    uint2 v = *(uint2*)vp;
    __half2 v01 = *(__half2*)&v.x, v23 = *(__half2*)&v.y;
    uint2 o;
    o.x = packh2(__half2float(v01.x) * rv.x, __half2float(v01.y) * rv.y);
    o.y = packh2(__half2float(v23.x) * rv.z, __half2float(v23.y) * rv.w);
    *(uint2*)vp = o;
}

// ---------------- launch ----------------
extern "C" void kernel_launch(void* const* d_in, const int* in_sizes, int n_in,
                              void* d_out, int out_size) {
    const float* x = (const float*)d_in[0];
    const float* ctx = (const float*)d_in[1];
    const unsigned char* mask_raw = (const unsigned char*)d_in[2];
    const unsigned char* mctx_raw = (const unsigned char*)d_in[3];
    const float* qw = (const float*)d_in[4];
    const float* qb = (const float*)d_in[5];
    const float* kw = (const float*)d_in[6];
    const float* kb = (const float*)d_in[7];
    const float* vw = (const float*)d_in[8];
    const float* vb = (const float*)d_in[9];
    const float* ow = (const float*)d_in[10];
    const float* ob = (const float*)d_in[11];
    const float* gq = (const float*)d_in[12];
    const float* bq = (const float*)d_in[13];
    const float* gk = (const float*)d_in[14];
    const float* bk = (const float*)d_in[15];
    const float* gv = (const float*)d_in[16];
    const float* bv = (const float*)d_in[17];
    float* out = (float*)d_out;

    __half *wnq, *wnkv, *wno, *xr, *cr, *qbuf, *kbuf, *vbuf, *pbuf, *abuf;
    float *rpbuf, *rbuf;
    unsigned char *mask, *mctx;
    cudaGetSymbolAddress((void**)&wnq, g_wnq);
    cudaGetSymbolAddress((void**)&wnkv, g_wnkv);
    cudaGetSymbolAddress((void**)&wno, g_wno);
    cudaGetSymbolAddress((void**)&xr, g_xr);
    cudaGetSymbolAddress((void**)&cr, g_cr);
    cudaGetSymbolAddress((void**)&qbuf, g_q);
    cudaGetSymbolAddress((void**)&kbuf, g_k);
    cudaGetSymbolAddress((void**)&vbuf, g_v);
    cudaGetSymbolAddress((void**)&pbuf, g_p);
    cudaGetSymbolAddress((void**)&rpbuf, g_rp);
    cudaGetSymbolAddress((void**)&rbuf, g_r);
    cudaGetSymbolAddress((void**)&abuf, g_att);
    cudaGetSymbolAddress((void**)&mask, g_mask);
    cudaGetSymbolAddress((void**)&mctx, g_mctx);

    __half* wnk = wnkv;
    __half* wnv = wnkv + EDIM * CDIM;

    const int SM_PROJ = 3 * (128 + 128) * 72 * 2;   // 110592, NS=3
    const int SM_SC = 2 * (128 + 128) * 72 * 2;     // 73728,  NS=2 (R12 config, 256 thr)
    const int SM_AV = 2 * (256 + 64) * 72 * 2;      // 92160,  NS=2
    const int SM_OP = 3 * (128 + 128) * 72 * 2;     // 110592, NS=3
    cudaFuncSetAttribute((const void*)mma_gemm<0, 128, 128, 64, 3, 2, 128>,
                         cudaFuncAttributeMaxDynamicSharedMemorySize, SM_PROJ);
    cudaFuncSetAttribute((const void*)mma_gemm<3, 128, 128, 32, 2, 2, 256>,
                         cudaFuncAttributeMaxDynamicSharedMemorySize, SM_SC);
    cudaFuncSetAttribute((const void*)mma_gemm<2, 256, 64, 64, 2, 2, 128>,
                         cudaFuncAttributeMaxDynamicSharedMemorySize, SM_AV);
    cudaFuncSetAttribute((const void*)mma_gemm<0, 128, 128, 64, 3, 4, 128>,
                         cudaFuncAttributeMaxDynamicSharedMemorySize, SM_OP);

    // 0+1. preamble: canon masks + transpose/round x,ctx + weight standardization
    preamble_kernel<<<2 + NB_TX + NB_TC + 4 * EDIM, 256>>>(
        x, ctx, mask_raw, mctx_raw, qw, kw, vw, ow,
        xr, cr, mask, mctx, wnq, wnkv, wno);

    // 2. merged Q + K + V projections: one launch, y-dispatch 8|8|8
    GP pQ = { xr, 1, (long)TLEN * EDIM, 0, EDIM,
              wnq, 1, 0, 0, EDIM,
              qbuf, 1, (long)TLEN * EDIM, 0, EDIM,
              EDIM, qb, 0, mask, 1, 1, TLEN, nullptr, 0, nullptr };
    GP pK = { cr, 1, (long)SLEN * CDIM, 0, CDIM,
              wnk, 1, 0, 0, CDIM,
              kbuf, 1, (long)SLEN * EDIM, 0, EDIM,
              CDIM, kb, 0, mctx, 1, 1, SLEN, nullptr, 0, nullptr };
    GP pV = { wnv, 1, 0, 0, CDIM,
              cr, 1, (long)SLEN * CDIM, 0, CDIM,
              vbuf, 1, (long)EDIM * SLEN, 0, SLEN,
              CDIM, vb, 1, mctx, 0, 1, SLEN, nullptr, 0, nullptr };
    mma_gemm<0, 128, 128, 64, 3, 2, 128><<<dim3(8, 24, BATCH), 128, SM_PROJ>>>(pQ, pK, pV, 8, 16);

    // 3. per-head LayerNorm over dh (q scaled by 1/256)
    ln_kernel<<<dim3(TLEN / 128, 3 * BATCH * NH), 128>>>(qbuf, kbuf, vbuf,
                                                         gq, bq, gk, bk, gv, bv);

    // 4. P[t,s] = mask[t] ? exp(sum_d q'[t,d] k[s,d]) : 0, + column partials -> rp
    //    R12 tile (128x128, NS=2) but 256 threads / 8 warps (4Mx2N, WM=32)
    GP pS = { qbuf, NH, (long)TLEN * EDIM, DH, EDIM,
              kbuf, NH, (long)SLEN * EDIM, DH, EDIM,
              pbuf, 1, (long)TLEN * SLEN, 0, SLEN,
              DH, nullptr, 0, mask, 1, NH, TLEN, nullptr, 0, rpbuf };
    mma_gemm<3, 128, 128, 32, 2, 2, 256><<<dim3(SLEN / 128, TLEN / 128, BATCH * NH), 256, SM_SC>>>(
        pS, pS, pS, 1 << 30, 1 << 30);

    // 5. finalize r; v' = v * r
    finalize_r<<<BATCH * NH * SLEN / 256, 256>>>(rpbuf, rbuf, mctx);
    vscale_kernel<<<BATCH * EDIM * SLEN / 4 / 256, 256>>>(vbuf, rbuf);

    // 6. att[t,d] = sum_s P[t,s] v'[d,s]  -> att [B][T][E] (256x64 tiles, R12 config)
    GP pA = { pbuf, 1, (long)TLEN * SLEN, 0, SLEN,
              vbuf, NH, (long)EDIM * SLEN, (long)DH * SLEN, SLEN,
              abuf, NH, (long)TLEN * EDIM, DH, EDIM,
              SLEN, nullptr, 0, mask, 1, 1, TLEN, nullptr, 0, nullptr };
    mma_gemm<2, 256, 64, 64, 2, 2, 128><<<dim3(1, TLEN / 256, BATCH * NH), 128, SM_AV>>>(
        pA, pA, pA, 1 << 30, 1 << 30);

    // 7. out[e,t] = sum_e' wno[e,e'] att[t,e'] + ob + mask + x
    GP pO = { wno, 1, 0, 0, EDIM,
              abuf, 1, (long)TLEN * EDIM, 0, EDIM,
              out, 1, (long)EDIM * TLEN, 0, TLEN,
              EDIM, ob, 1, mask, 0, 1, TLEN, x, (long)EDIM * TLEN, nullptr };
    mma_gemm<0, 128, 128, 64, 3, 4, 128><<<dim3(TLEN / 128, EDIM / 128, BATCH), 128, SM_OP>>>(
        pO, pO, pO, 1 << 30, 1 << 30);
}

// round 17
// speedup vs baseline: 1.0984x; 1.0548x over previous
#include <cuda_runtime.h>
#include <cuda_fp16.h>
#include <cstdint>

#define BATCH 4
#define EDIM 1024
#define CDIM 768
#define TLEN 1024
#define SLEN 1024
#define NH 16
#define DH 64
#define EPSV 1e-5f

// ---------------- scratch (static device globals; no allocation) ----------------
__device__ __half g_wnq[EDIM * EDIM];
__device__ __half g_wnkv[2 * EDIM * CDIM];              // [wnk ; wnv]
__device__ __half g_wno[EDIM * EDIM];
__device__ __half g_xr[BATCH * TLEN * EDIM];            // x^T  [B][T][E] fp16
__device__ __half g_cr[BATCH * SLEN * CDIM];            // ctx^T [B][S][C] fp16
__device__ __half g_q[BATCH * TLEN * EDIM];             // q [B][T][E]
__device__ __half g_k[BATCH * SLEN * EDIM];             // k [B][S][E]
__device__ __half g_v[BATCH * EDIM * SLEN];             // v [B][E][S]
__device__ __half g_p[(long)BATCH * NH * TLEN * SLEN];  // P [b,h][t][s] fp16
__device__ float g_rp[BATCH * NH * SLEN * 8];           // per-t-tile column partials
__device__ float g_r[BATCH * NH * SLEN];                // 1/rowsum (or 0)
__device__ __half g_att[BATCH * TLEN * EDIM];           // att [B][T][E]
__device__ unsigned char g_mask[BATCH * TLEN];
__device__ unsigned char g_mctx[BATCH * SLEN];

__device__ __forceinline__ uint32_t smem_u32(const void* p) {
    uint32_t a;
    asm("{ .reg .u64 t; cvta.to.shared.u64 t, %1; cvt.u32.u64 %0, t; }" : "=r"(a) : "l"(p));
    return a;
}
__device__ __forceinline__ uint32_t packh2(float lo, float hi) {
    __half2 h = __floats2half2_rn(lo, hi);
    return *(uint32_t*)&h;
}
#define CP16(dst, src) asm volatile("cp.async.cg.shared.global [%0], [%1], 16;" :: "r"(dst), "l"(src))
#define CPCOMMIT()     asm volatile("cp.async.commit_group;" ::: "memory")
#define CPWAIT(N)      asm volatile("cp.async.wait_group %0;" :: "n"(N) : "memory")

#define MMA_F16(d, a, b) \
    asm volatile("mma.sync.aligned.m16n8k16.row.col.f32.f16.f16.f32 " \
                 "{%0,%1,%2,%3}, {%4,%5,%6,%7}, {%8,%9}, {%0,%1,%2,%3};" \
                 : "+f"((d)[0]), "+f"((d)[1]), "+f"((d)[2]), "+f"((d)[3]) \
                 : "r"((a)[0]), "r"((a)[1]), "r"((a)[2]), "r"((a)[3]), \
                   "r"((b)[0]), "r"((b)[1]))

#define LDSM4(r0, r1, r2, r3, addr) \
    asm volatile("ldmatrix.sync.aligned.m8n8.x4.shared.b16 {%0,%1,%2,%3}, [%4];" \
                 : "=r"(r0), "=r"(r1), "=r"(r2), "=r"(r3) : "r"(addr))

// ---------------- GEMM parameter set ----------------
struct GP {
    const void* A; int aDiv; long aStrZa, aStrZb; int lda;
    const void* B; int bDiv; long bStrZa, bStrZb; int ldb;
    void* C; int cDiv; long cStrZa, cStrZb; int ldc;
    int K;
    const float* bias; int biasOnM;
    const unsigned char* mask; int maskOnM; int maskDiv; int maskLd;
    const float* res; long resStride;
    float* rp;                       // EPI==3 only: column-partial buffer
};

// ================= fp16 mma GEMM body: BK=64, single-sync pipeline =================
template <int EPI, int BM, int BN, int WM, int NS, int CBYTES, int NT>
__device__ __forceinline__ void gemm_body(const GP& P, int ytile) {
    constexpr int BK = 64;
    constexpr int STR = BK + 8;
    constexpr int AFL = BM * STR;
    constexpr int BFL = BN * STR;
    constexpr int STG = AFL + BFL;
    constexpr int NWM = BM / WM;
    constexpr int MF = WM / 16;
    constexpr int NF = 8;

    extern __shared__ char smch[];
    uint32_t sbase = smem_u32(smch);
    int tid = threadIdx.x, wid = tid >> 5, lane = tid & 31;
    int z = blockIdx.z;
    const __half* A = (const __half*)P.A + (z / P.aDiv) * P.aStrZa + (z % P.aDiv) * P.aStrZb;
    const __half* B = (const __half*)P.B + (z / P.bDiv) * P.bStrZa + (z % P.bDiv) * P.bStrZb;
    long mBase = (long)ytile * BM, nBase = (long)blockIdx.x * BN;
    int lda = P.lda, ldb = P.ldb, ldc = P.ldc;

    float acc[MF][NF][4];
#pragma unroll
    for (int i = 0; i < MF; ++i)
#pragma unroll
        for (int j = 0; j < NF; ++j)
#pragma unroll
            for (int t = 0; t < 4; ++t) acc[i][j][t] = 0.f;

    int nIter = P.K / BK;

    auto issue = [&](int stage, int k0) {
        uint32_t aoff = sbase + stage * STG * 2;
#pragma unroll
        for (int r = 0; r < BM * 8 / NT; ++r) {
            int lin = tid + NT * r;
            int m = lin >> 3, kc = (lin & 7) * 8;
            CP16(aoff + (m * STR + kc) * 2, &A[(mBase + m) * (long)lda + k0 + kc]);
        }
        uint32_t boff = sbase + (stage * STG + AFL) * 2;
#pragma unroll
        for (int r = 0; r < BN * 8 / NT; ++r) {
            int lin = tid + NT * r;
            int n = lin >> 3, kc = (lin & 7) * 8;
            CP16(boff + (n * STR + kc) * 2, &B[(nBase + n) * (long)ldb + k0 + kc]);
        }
    };

    int warpM = wid % NWM, warpN = wid / NWM;
    int mW = warpM * WM, nW = warpN * 64;
    int c4 = lane & 3, r4 = lane >> 2;
    int quad = lane >> 3, lrow = lane & 7;

    uint32_t aRole[MF], bRole[NF / 2];
#pragma unroll
    for (int mf = 0; mf < MF; ++mf)
        aRole[mf] = (uint32_t)((mW + 16 * mf + (quad & 1) * 8 + lrow) * STR + (quad >> 1) * 8);
#pragma unroll
    for (int p = 0; p < NF / 2; ++p)
        bRole[p] = (uint32_t)((nW + 16 * p + (quad >> 1) * 8 + lrow) * STR + (quad & 1) * 8);

    auto compute = [&](int stage) {
        uint32_t As_b = sbase + stage * STG * 2;
        uint32_t Bs_b = As_b + AFL * 2;
#pragma unroll
        for (int kk = 0; kk < BK; kk += 16) {
            uint32_t a[MF][4];
#pragma unroll
            for (int mf = 0; mf < MF; ++mf)
                LDSM4(a[mf][0], a[mf][1], a[mf][2], a[mf][3], As_b + (aRole[mf] + kk) * 2);
            uint32_t b[NF][2];
#pragma unroll
            for (int p = 0; p < NF / 2; ++p)
                LDSM4(b[2 * p][0], b[2 * p][1], b[2 * p + 1][0], b[2 * p + 1][1],
                      Bs_b + (bRole[p] + kk) * 2);
#pragma unroll
            for (int mf = 0; mf < MF; ++mf)
#pragma unroll
                for (int nf = 0; nf < NF; ++nf)
                    MMA_F16(acc[mf][nf], a[mf], b[nf]);
        }
    };

    for (int s = 0; s < NS - 1; ++s) {
        if (s < nIter) issue(s, s * BK);
        CPCOMMIT();
    }
    for (int it = 0; it < nIter; ++it) {
        CPWAIT(NS - 2);
        __syncthreads();
        compute(it % NS);
        int nx = it + NS - 1;
        if (nx < nIter) issue(nx % NS, nx * BK);
        CPCOMMIT();
    }

    // ---- epilogue ----
    int mb = z / P.maskDiv;
    float bn[NF][2];
    unsigned char mn[NF][2];
    if (EPI == 0) {
#pragma unroll
        for (int nf = 0; nf < NF; ++nf) {
            long n = nBase + nW + nf * 8 + 2 * c4;
            bn[nf][0] = P.biasOnM ? 0.f : P.bias[n];
            bn[nf][1] = P.biasOnM ? 0.f : P.bias[n + 1];
            mn[nf][0] = P.maskOnM ? 1 : P.mask[(long)mb * P.maskLd + n];
            mn[nf][1] = P.maskOnM ? 1 : P.mask[(long)mb * P.maskLd + n + 1];
        }
    }
    float rsumN[NF * 2];
#pragma unroll
    for (int q = 0; q < NF * 2; ++q) rsumN[q] = 0.f;

#pragma unroll
    for (int mf = 0; mf < MF; ++mf) {
#pragma unroll
        for (int half = 0; half < 2; ++half) {
            long m = mBase + mW + mf * 16 + r4 + half * 8;
            float bvm = (EPI == 0 && P.biasOnM) ? P.bias[m] : 0.f;
            bool mOK = true;
            if ((EPI == 0 || EPI == 3) && P.maskOnM)
                mOK = P.mask[(long)mb * P.maskLd + m] != 0;
#pragma unroll
            for (int nf = 0; nf < NF; ++nf) {
                long n = nBase + nW + nf * 8 + 2 * c4;
                float v0 = acc[mf][nf][half * 2 + 0];
                float v1 = acc[mf][nf][half * 2 + 1];
                if (EPI == 0) {
                    if (P.biasOnM) { v0 += bvm; v1 += bvm; }
                    else { v0 += bn[nf][0]; v1 += bn[nf][1]; }
                    if (P.maskOnM) { if (!mOK) { v0 = 0.f; v1 = 0.f; } }
                    else { if (!mn[nf][0]) v0 = 0.f; if (!mn[nf][1]) v1 = 0.f; }
                } else if (EPI == 3) {
                    __half h0 = __float2half_rn(__expf(v0));
                    __half h1 = __float2half_rn(__expf(v1));
                    v0 = mOK ? __half2float(h0) : 0.f;
                    v1 = mOK ? __half2float(h1) : 0.f;
                    rsumN[nf * 2 + 0] += v0;
                    rsumN[nf * 2 + 1] += v1;
                }
                if (CBYTES == 4) {
                    float* Cf = (float*)P.C + (z / P.cDiv) * P.cStrZa + (z % P.cDiv) * P.cStrZb;
                    if (EPI == 0 && P.res) {
                        v0 += P.res[z * P.resStride + m * ldc + n];
                        v1 += P.res[z * P.resStride + m * ldc + n + 1];
                    }
                    float2 o; o.x = v0; o.y = v1;
                    *(float2*)&Cf[m * ldc + n] = o;
                } else {
                    __half* Ch = (__half*)P.C + (z / P.cDiv) * P.cStrZa + (z % P.cDiv) * P.cStrZb;
                    *(uint32_t*)&Ch[m * ldc + n] = packh2(v0, v1);
                }
            }
        }
    }
    if (EPI == 3) {
#pragma unroll
        for (int q = 0; q < NF * 2; ++q) {
            float v = rsumN[q];
            v += __shfl_xor_sync(0xFFFFFFFFu, v, 4);
            v += __shfl_xor_sync(0xFFFFFFFFu, v, 8);
            v += __shfl_xor_sync(0xFFFFFFFFu, v, 16);
            rsumN[q] = v;
        }
        __syncthreads();
        float* red = (float*)smch;           // [NWM][BN]
        if (r4 == 0) {
#pragma unroll
            for (int nf = 0; nf < NF; ++nf) {
                int nl = nW + nf * 8 + 2 * c4;
                red[warpM * BN + nl] = rsumN[nf * 2 + 0];
                red[warpM * BN + nl + 1] = rsumN[nf * 2 + 1];
            }
        }
        __syncthreads();
        if (tid < BN) {
            float s = red[tid];
#pragma unroll
            for (int w = 1; w < NWM; ++w) s += red[w * BN + tid];
            P.rp[((long)z * SLEN + nBase + tid) * 8 + ytile] = s;
        }
    }
}

template <int EPI, int BM, int BN, int WM, int NS, int CBYTES, int NT>
__global__ __launch_bounds__(NT) void mma_gemm(GP p0, GP p1, GP p2, int y1, int y2) {
    int y = blockIdx.y;
    if (y < y1) gemm_body<EPI, BM, BN, WM, NS, CBYTES, NT>(p0, y);
    else if (y < y2) gemm_body<EPI, BM, BN, WM, NS, CBYTES, NT>(p1, y - y1);
    else gemm_body<EPI, BM, BN, WM, NS, CBYTES, NT>(p2, y - y2);
}

// ================= preamble megakernel =================
__device__ void canon_body(const unsigned char* __restrict__ raw,
                           unsigned char* __restrict__ out, int n, int* flag) {
    if (threadIdx.x == 0) *flag = 0;
    __syncthreads();
    int local = 0;
    for (int i = threadIdx.x; i < n; i += 256)
        if ((i & 3) != 0 && raw[i] != 0) local = 1;
    if (local) atomicOr(flag, 1);
    __syncthreads();
    bool is_bool = (*flag != 0);
    for (int i = threadIdx.x; i < n; i += 256)
        out[i] = is_bool ? raw[i] : raw[4 * i];
}

__device__ void transpose_body(const float* __restrict__ in, __half* __restrict__ out,
                               int R, int C, int idx, float* tile) {
    int nxb = C / 32;
    int per = nxb * (R / 32);
    int b = idx / per;
    int rem = idx % per;
    int by = rem / nxb, bx = rem % nxb;
    const float* src = in + (long)b * R * C;
    __half* dst = out + (long)b * R * C;
    int c0 = bx * 32, r0 = by * 32;
    int tx = threadIdx.x & 31, ty = threadIdx.x >> 5;
#pragma unroll
    for (int i = 0; i < 32; i += 8)
        tile[(ty + i) * 33 + tx] = src[(long)(r0 + ty + i) * C + c0 + tx];
    __syncthreads();
#pragma unroll
    for (int i = 0; i < 32; i += 8)
        dst[(long)(c0 + ty + i) * R + r0 + tx] = __float2half_rn(tile[tx * 33 + ty + i]);
}

__device__ void ws_body(const float* __restrict__ w, __half* __restrict__ outp,
                        int I, int o, float* sh) {
    const float* row = w + (long)o * I;
    float s = 0.f, ss = 0.f;
    for (int i = threadIdx.x; i < I; i += 256) {
        float v = row[i];
        s += v; ss += v * v;
    }
#pragma unroll
    for (int off = 16; off; off >>= 1) {
        s += __shfl_xor_sync(0xFFFFFFFFu, s, off);
        ss += __shfl_xor_sync(0xFFFFFFFFu, ss, off);
    }
    int wid = threadIdx.x >> 5;
    if ((threadIdx.x & 31) == 0) { sh[wid] = s; sh[8 + wid] = ss; }
    __syncthreads();
    if (threadIdx.x == 0) {
        float ts = 0.f, tss = 0.f;
        for (int i = 0; i < 8; i++) { ts += sh[i]; tss += sh[8 + i]; }
        float mu = ts / (float)I;
        float var = tss / (float)I - mu * mu;
        sh[0] = mu; sh[1] = rsqrtf(var + EPSV);
    }
    __syncthreads();
    float mu = sh[0], inv = sh[1];
    for (int i = threadIdx.x; i < I; i += 256)
        outp[(long)o * I + i] = __float2half_rn((row[i] - mu) * inv);
}

#define NB_TX (32 * 32 * BATCH)
#define NB_TC (32 * 24 * BATCH)
__global__ __launch_bounds__(256) void preamble_kernel(
    const float* __restrict__ x, const float* __restrict__ ctx,
    const unsigned char* __restrict__ mask_raw, const unsigned char* __restrict__ mctx_raw,
    const float* __restrict__ qw, const float* __restrict__ kw,
    const float* __restrict__ vw, const float* __restrict__ ow,
    __half* __restrict__ xr, __half* __restrict__ cr,
    unsigned char* __restrict__ mask, unsigned char* __restrict__ mctx,
    __half* __restrict__ wnq, __half* __restrict__ wnkv, __half* __restrict__ wno)
{
    __shared__ float shm[32 * 33];
    int b = blockIdx.x;
    if (b < 2) {
        canon_body(b ? mctx_raw : mask_raw, b ? mctx : mask, BATCH * TLEN, (int*)shm);
    } else if (b < 2 + NB_TX) {
        transpose_body(x, xr, EDIM, TLEN, b - 2, shm);
    } else if (b < 2 + NB_TX + NB_TC) {
        transpose_body(ctx, cr, CDIM, SLEN, b - 2 - NB_TX, shm);
    } else {
        int idx = b - 2 - NB_TX - NB_TC;
        int c = idx >> 10, o = idx & 1023;
        const float* w; __half* outp; int I;
        if (c == 0) { w = qw; outp = wnq; I = EDIM; }
        else if (c == 1) { w = kw; outp = wnkv; I = CDIM; }
        else if (c == 2) { w = vw; outp = wnkv + EDIM * CDIM; I = CDIM; }
        else { w = ow; outp = wno; I = EDIM; }
        ws_body(w, outp, I, o, shm);
    }
}

// ---------------- per-head LayerNorm over dh=64 ----------------
// c = cBase + blockIdx.y/(B*NH): 0 = q (scale 1/256), 1 = k, 2 = v (strided)
__global__ void ln_kernel(__half* __restrict__ qbuf, __half* __restrict__ kbuf,
                          __half* __restrict__ vbuf, int cBase,
                          const float* __restrict__ gq, const float* __restrict__ bq,
                          const float* __restrict__ gk, const float* __restrict__ bk,
                          const float* __restrict__ gv, const float* __restrict__ bv) {
    int c = cBase + blockIdx.y / (BATCH * NH);
    int bh = blockIdx.y % (BATCH * NH);
    int b = bh / NH, h = bh % NH;
    int l = blockIdx.x * blockDim.x + threadIdx.x;
    float vals[DH];
    float s = 0.f, ss = 0.f;
    if (c < 2) {
        __half* base = (c == 0 ? qbuf : kbuf) + ((long)b * TLEN + l) * EDIM + h * DH;
        const float* g = c == 0 ? gq : gk;
        const float* bt = c == 0 ? bq : bk;
        float scale = c == 0 ? (1.f / 256.f) : 1.f;
#pragma unroll
        for (int i = 0; i < 8; ++i) {
            uint4 u = ((const uint4*)base)[i];
            const __half2* hp = (const __half2*)&u;
#pragma unroll
            for (int j = 0; j < 4; ++j) {
                float2 f = __half22float2(hp[j]);
                vals[i * 8 + j * 2] = f.x;
                vals[i * 8 + j * 2 + 1] = f.y;
                s += f.x + f.y;
                ss += f.x * f.x + f.y * f.y;
            }
        }
        float mu = s * (1.f / DH);
        float var = ss * (1.f / DH) - mu * mu;
        float inv = rsqrtf(var + EPSV);
#pragma unroll
        for (int i = 0; i < 8; ++i) {
            uint4 u;
            uint32_t* up = (uint32_t*)&u;
#pragma unroll
            for (int j = 0; j < 4; ++j) {
                int d0 = i * 8 + j * 2;
                up[j] = packh2(((vals[d0] - mu) * inv * g[d0] + bt[d0]) * scale,
                               ((vals[d0 + 1] - mu) * inv * g[d0 + 1] + bt[d0 + 1]) * scale);
            }
            ((uint4*)base)[i] = u;
        }
    } else {
        __half* base = vbuf + (long)b * EDIM * SLEN + (long)h * DH * SLEN + l;
#pragma unroll
        for (int d = 0; d < DH; d++) {
            float v = __half2float(base[(long)d * SLEN]);
            vals[d] = v;
            s += v; ss += v * v;
        }
        float mu = s * (1.f / DH);
        float var = ss * (1.f / DH) - mu * mu;
        float inv = rsqrtf(var + EPSV);
#pragma unroll
        for (int d = 0; d < DH; d++)
            base[(long)d * SLEN] = __float2half_rn((vals[d] - mu) * inv * gv[d] + bv[d]);
    }
}

// ---------------- finalize r ----------------
__global__ void finalize_r(const float* __restrict__ rp, float* __restrict__ r,
                           const unsigned char* __restrict__ mctx) {
    int i = blockIdx.x * blockDim.x + threadIdx.x;
    float4 a = ((const float4*)rp)[i * 2];
    float4 b = ((const float4*)rp)[i * 2 + 1];
    float s = ((a.x + a.y) + (a.z + a.w)) + ((b.x + b.y) + (b.z + b.w));
    int bidx = i >> 14, sidx = i & (SLEN - 1);
    r[i] = (mctx[bidx * SLEN + sidx] && s > 0.f) ? (1.f / s) : 0.f;
}

// ---------------- v' = h(v * r[b,h,s]) in-place (fp16) ----------------
__global__ void vscale_kernel(__half* __restrict__ vbuf, const float* __restrict__ r) {
    long i = (long)blockIdx.x * blockDim.x + threadIdx.x;
    long fi = i * 4;
    int b = (int)(fi / ((long)EDIM * SLEN));
    long rem = fi % ((long)EDIM * SLEN);
    int e = (int)(rem / SLEN), s = (int)(rem % SLEN);
    int h = e / DH;
    __half* vp = vbuf + (long)b * EDIM * SLEN + (long)e * SLEN + s;
    float4 rv = *(const float4*)&r[((long)b * NH + h) * SLEN + s];
    uint2 v = *(uint2*)vp;
    __half2 v01 = *(__half2*)&v.x, v23 = *(__half2*)&v.y;
    uint2 o;
    o.x = packh2(__half2float(v01.x) * rv.x, __half2float(v01.y) * rv.y);
    o.y = packh2(__half2float(v23.x) * rv.z, __half2float(v23.y) * rv.w);
    *(uint2*)vp = o;
}

// ---------------- launch ----------------
extern "C" void kernel_launch(void* const* d_in, const int* in_sizes, int n_in,
                              void* d_out, int out_size) {
    const float* x = (const float*)d_in[0];
    const float* ctx = (const float*)d_in[1];
    const unsigned char* mask_raw = (const unsigned char*)d_in[2];
    const unsigned char* mctx_raw = (const unsigned char*)d_in[3];
    const float* qw = (const float*)d_in[4];
    const float* qb = (const float*)d_in[5];
    const float* kw = (const float*)d_in[6];
    const float* kb = (const float*)d_in[7];
    const float* vw = (const float*)d_in[8];
    const float* vb = (const float*)d_in[9];
    const float* ow = (const float*)d_in[10];
    const float* ob = (const float*)d_in[11];
    const float* gq = (const float*)d_in[12];
    const float* bq = (const float*)d_in[13];
    const float* gk = (const float*)d_in[14];
    const float* bk = (const float*)d_in[15];
    const float* gv = (const float*)d_in[16];
    const float* bv = (const float*)d_in[17];
    float* out = (float*)d_out;

    __half *wnq, *wnkv, *wno, *xr, *cr, *qbuf, *kbuf, *vbuf, *pbuf, *abuf;
    float *rpbuf, *rbuf;
    unsigned char *mask, *mctx;
    cudaGetSymbolAddress((void**)&wnq, g_wnq);
    cudaGetSymbolAddress((void**)&wnkv, g_wnkv);
    cudaGetSymbolAddress((void**)&wno, g_wno);
    cudaGetSymbolAddress((void**)&xr, g_xr);
    cudaGetSymbolAddress((void**)&cr, g_cr);
    cudaGetSymbolAddress((void**)&qbuf, g_q);
    cudaGetSymbolAddress((void**)&kbuf, g_k);
    cudaGetSymbolAddress((void**)&vbuf, g_v);
    cudaGetSymbolAddress((void**)&pbuf, g_p);
    cudaGetSymbolAddress((void**)&rpbuf, g_rp);
    cudaGetSymbolAddress((void**)&rbuf, g_r);
    cudaGetSymbolAddress((void**)&abuf, g_att);
    cudaGetSymbolAddress((void**)&mask, g_mask);
    cudaGetSymbolAddress((void**)&mctx, g_mctx);

    __half* wnk = wnkv;
    __half* wnv = wnkv + EDIM * CDIM;

    // fork/join resources (created on first, non-captured call; reused by capture)
    static cudaStream_t sV = nullptr;
    static cudaEvent_t eFork = nullptr, eV = nullptr;
    if (!sV) {
        cudaStreamCreateWithFlags(&sV, cudaStreamNonBlocking);
        cudaEventCreateWithFlags(&eFork, cudaEventDisableTiming);
        cudaEventCreateWithFlags(&eV, cudaEventDisableTiming);
    }

    const int SM_PROJ = 3 * (128 + 128) * 72 * 2;   // 110592, NS=3
    const int SM_SC = 2 * (128 + 128) * 72 * 2;     // 73728,  NS=2 (R12 config)
    const int SM_AV = 2 * (256 + 64) * 72 * 2;      // 92160,  NS=2
    const int SM_OP = 3 * (128 + 128) * 72 * 2;     // 110592, NS=3
    cudaFuncSetAttribute((const void*)mma_gemm<0, 128, 128, 64, 3, 2, 128>,
                         cudaFuncAttributeMaxDynamicSharedMemorySize, SM_PROJ);
    cudaFuncSetAttribute((const void*)mma_gemm<3, 128, 128, 64, 2, 2, 128>,
                         cudaFuncAttributeMaxDynamicSharedMemorySize, SM_SC);
    cudaFuncSetAttribute((const void*)mma_gemm<2, 256, 64, 64, 2, 2, 128>,
                         cudaFuncAttributeMaxDynamicSharedMemorySize, SM_AV);
    cudaFuncSetAttribute((const void*)mma_gemm<0, 128, 128, 64, 3, 4, 128>,
                         cudaFuncAttributeMaxDynamicSharedMemorySize, SM_OP);

    // 0+1. preamble
    preamble_kernel<<<2 + NB_TX + NB_TC + 4 * EDIM, 256>>>(
        x, ctx, mask_raw, mctx_raw, qw, kw, vw, ow,
        xr, cr, mask, mctx, wnq, wnkv, wno);

    // fork: V pipeline on sV, QK+scores pipeline on default stream
    cudaEventRecord(eFork, 0);
    cudaStreamWaitEvent(sV, eFork, 0);

    GP pQ = { xr, 1, (long)TLEN * EDIM, 0, EDIM,
              wnq, 1, 0, 0, EDIM,
              qbuf, 1, (long)TLEN * EDIM, 0, EDIM,
              EDIM, qb, 0, mask, 1, 1, TLEN, nullptr, 0, nullptr };
    GP pK = { cr, 1, (long)SLEN * CDIM, 0, CDIM,
              wnk, 1, 0, 0, CDIM,
              kbuf, 1, (long)SLEN * EDIM, 0, EDIM,
              CDIM, kb, 0, mctx, 1, 1, SLEN, nullptr, 0, nullptr };
    GP pV = { wnv, 1, 0, 0, CDIM,
              cr, 1, (long)SLEN * CDIM, 0, CDIM,
              vbuf, 1, (long)EDIM * SLEN, 0, SLEN,
              CDIM, vb, 1, mctx, 0, 1, SLEN, nullptr, 0, nullptr };

    // sV branch: V projection + LN(v)
    mma_gemm<0, 128, 128, 64, 3, 2, 128><<<dim3(8, 8, BATCH), 128, SM_PROJ, sV>>>(
        pV, pV, pV, 1 << 30, 1 << 30);
    ln_kernel<<<dim3(TLEN / 128, BATCH * NH), 128, 0, sV>>>(qbuf, kbuf, vbuf, 2,
                                                            gq, bq, gk, bk, gv, bv);
    cudaEventRecord(eV, sV);

    // default stream: Q+K projections, LN(q,k), scores, finalize_r
    mma_gemm<0, 128, 128, 64, 3, 2, 128><<<dim3(8, 16, BATCH), 128, SM_PROJ>>>(
        pQ, pK, pK, 8, 1 << 30);
    ln_kernel<<<dim3(TLEN / 128, 2 * BATCH * NH), 128>>>(qbuf, kbuf, vbuf, 0,
                                                         gq, bq, gk, bk, gv, bv);
    GP pS = { qbuf, NH, (long)TLEN * EDIM, DH, EDIM,
              kbuf, NH, (long)SLEN * EDIM, DH, EDIM,
              pbuf, 1, (long)TLEN * SLEN, 0, SLEN,
              DH, nullptr, 0, mask, 1, NH, TLEN, nullptr, 0, rpbuf };
    mma_gemm<3, 128, 128, 64, 2, 2, 128><<<dim3(SLEN / 128, TLEN / 128, BATCH * NH), 128, SM_SC>>>(
        pS, pS, pS, 1 << 30, 1 << 30);
    finalize_r<<<BATCH * NH * SLEN / 256, 256>>>(rpbuf, rbuf, mctx);

    // join: vscale needs LN(v) (sV) + finalize_r (s0)
    cudaStreamWaitEvent(0, eV, 0);
    vscale_kernel<<<BATCH * EDIM * SLEN / 4 / 256, 256>>>(vbuf, rbuf);

    // 6. att[t,d] = sum_s P[t,s] v'[d,s]
    GP pA = { pbuf, 1, (long)TLEN * SLEN, 0, SLEN,
              vbuf, NH, (long)EDIM * SLEN, (long)DH * SLEN, SLEN,
              abuf, NH, (long)TLEN * EDIM, DH, EDIM,
              SLEN, nullptr, 0, mask, 1, 1, TLEN, nullptr, 0, nullptr };
    mma_gemm<2, 256, 64, 64, 2, 2, 128><<<dim3(1, TLEN / 256, BATCH * NH), 128, SM_AV>>>(
        pA, pA, pA, 1 << 30, 1 << 30);

    // 7. out[e,t] = sum_e' wno[e,e'] att[t,e'] + ob + mask + x
    GP pO = { wno, 1, 0, 0, EDIM,
              abuf, 1, (long)TLEN * EDIM, 0, EDIM,
              out, 1, (long)EDIM * TLEN, 0, TLEN,
              EDIM, ob, 1, mask, 0, 1, TLEN, x, (long)EDIM * TLEN, nullptr };
    mma_gemm<0, 128, 128, 64, 3, 4, 128><<<dim3(TLEN / 128, EDIM / 128, BATCH), 128, SM_OP>>>(
        pO, pO, pO, 1 << 30, 1 << 30);
}